// round 1
// baseline (speedup 1.0000x reference)
#include <cuda_runtime.h>
#include <math.h>

#define NATOMS 100000
#define MNBR   12
#define NEDGE  (NATOMS*MNBR)
#define ORIG   92
#define NBRD   41
#define FDIM   64
#define HFD    128
#define NCONVL 3
#define BQ     500
#define NPC    200
#define Y0C    0.28209479177387814f
#define TPN    0.125f
#define EPSB   1e-5f

// ---------------- scratch (no cudaMalloc allowed) ----------------
__device__ float g_x[NATOMS*FDIM];
__device__ float g_s[NATOMS*FDIM];
__device__ float g_y[NATOMS*FDIM];
__device__ float g_w0[3*NEDGE];
__device__ float g_bnsum[2*FDIM];

__device__ __forceinline__ float softplus_f(float z) {
    float t = fabsf(z);
    float e = __expf(-t);
    return fmaxf(z, 0.0f) + __logf(1.0f + e);
}

// =============== fused 3-layer edge kernel =====================
// w0[l][e] = Y0/M * ( sum_j softplus( nbr[e]·rW1[l][:,j] + rb1[l][j] ) * rW2[l][j,0] + rb2[l][0] )
// f32x2 packed: each thread handles 2 edges.
#define EPB 256
__global__ __launch_bounds__(128, 2) void edge_kernel(
    const float* __restrict__ nbr_fea, const float* __restrict__ rW1,
    const float* __restrict__ rb1, const float* __restrict__ rW2,
    const float* __restrict__ rb2)
{
    extern __shared__ float smf[];
    float2* sWd  = (float2*)smf;          // [41][123] duplicated: sWd[k*123+j]
    float2* sb1d = sWd + 41*123;          // [123]
    float2* sw2d = sb1d + 123;            // [123]  (rW2 col0 * Y0/M, duplicated)
    float*  sIn  = (float*)(sw2d + 123);  // [256][41]
    const int tid = threadIdx.x;

    for (int i = tid; i < 41*123; i += 128) {
        int k = i / 123, j = i % 123;
        int l = j / 41, jj = j % 41;
        float w = rW1[(l*41 + k)*41 + jj];
        sWd[i] = make_float2(w, w);
    }
    for (int i = tid; i < 123; i += 128) {
        float b = rb1[i];
        sb1d[i] = make_float2(b, b);
        int l = i / 41, jj = i % 41;
        float w2 = rW2[(l*41 + jj)*9] * (Y0C / (float)MNBR);
        sw2d[i] = make_float2(w2, w2);
    }
    int base = blockIdx.x * (EPB*NBRD);
    for (int i = tid; i < EPB*NBRD; i += 128) {
        int g = base + i;
        sIn[i] = (g < NEDGE*NBRD) ? nbr_fea[g] : 0.0f;
    }
    __syncthreads();

    unsigned long long in2[41];
    #pragma unroll
    for (int k = 0; k < 41; k++) {
        float a = sIn[tid*41 + k];
        float b = sIn[(tid + 128)*41 + k];
        asm("mov.b64 %0, {%1, %2};" : "=l"(in2[k]) : "f"(a), "f"(b));
    }
    const int e0 = blockIdx.x*EPB + tid;
    const int e1 = e0 + 128;

    for (int l = 0; l < 3; l++) {
        unsigned long long wacc = 0ULL;
        float r0 = rb2[l*9] * (Y0C / (float)MNBR);
        for (int j = 0; j < 41; j++) {
            const int col = l*41 + j;
            unsigned long long acc0 = *(const unsigned long long*)(sb1d + col);
            unsigned long long acc1 = 0ULL;
            const unsigned long long* wp = ((const unsigned long long*)sWd) + col;
            #pragma unroll
            for (int k = 0; k < 40; k += 2) {
                unsigned long long wA = wp[(size_t)k*123];
                asm("fma.rn.f32x2 %0, %1, %2, %3;" : "=l"(acc0) : "l"(wA), "l"(in2[k]),   "l"(acc0));
                unsigned long long wB = wp[(size_t)(k+1)*123];
                asm("fma.rn.f32x2 %0, %1, %2, %3;" : "=l"(acc1) : "l"(wB), "l"(in2[k+1]), "l"(acc1));
            }
            {
                unsigned long long wC = wp[(size_t)40*123];
                asm("fma.rn.f32x2 %0, %1, %2, %3;" : "=l"(acc0) : "l"(wC), "l"(in2[40]), "l"(acc0));
            }
            unsigned long long zz;
            asm("add.rn.f32x2 %0, %1, %2;" : "=l"(zz) : "l"(acc0), "l"(acc1));
            float z0, z1;
            asm("mov.b64 {%0, %1}, %2;" : "=f"(z0), "=f"(z1) : "l"(zz));
            float s0 = softplus_f(z0);
            float s1 = softplus_f(z1);
            unsigned long long sp2;
            asm("mov.b64 %0, {%1, %2};" : "=l"(sp2) : "f"(s0), "f"(s1));
            unsigned long long w2 = *((const unsigned long long*)(sw2d + col));
            asm("fma.rn.f32x2 %0, %1, %2, %3;" : "=l"(wacc) : "l"(w2), "l"(sp2), "l"(wacc));
        }
        float wa, wb;
        asm("mov.b64 {%0, %1}, %2;" : "=f"(wa), "=f"(wb) : "l"(wacc));
        g_w0[l*NEDGE + e0] = wa + r0;
        if (e1 < NEDGE) g_w0[l*NEDGE + e1] = wb + r0;
    }
}

// =============== embedding: x = atom_fea @ emb_W + emb_b =====================
__global__ __launch_bounds__(256) void embed_kernel(
    const float* __restrict__ A, const float* __restrict__ W, const float* __restrict__ bias)
{
    __shared__ float sA[64*93];
    __shared__ float sW[92*64];
    __shared__ float sB[64];
    const int tid = threadIdx.x;
    const int row0 = blockIdx.x * 64;
    for (int i = tid; i < 64*92; i += 256) {
        int r = i / 92, k = i % 92;
        int row = row0 + r;
        sA[r*93 + k] = (row < NATOMS) ? A[row*92 + k] : 0.0f;
    }
    for (int i = tid; i < 92*64; i += 256) sW[i] = W[i];
    if (tid < 64) sB[tid] = bias[tid];
    __syncthreads();
    const int tx = tid & 15, ty = tid >> 4;
    float acc[4][4];
    #pragma unroll
    for (int i = 0; i < 4; i++)
        #pragma unroll
        for (int j = 0; j < 4; j++) acc[i][j] = 0.0f;
    #pragma unroll 4
    for (int k = 0; k < 92; k++) {
        float4 bv = *(const float4*)(sW + k*64 + (tx << 2));
        float av[4];
        #pragma unroll
        for (int i = 0; i < 4; i++) av[i] = sA[(ty*4 + i)*93 + k];
        #pragma unroll
        for (int i = 0; i < 4; i++) {
            acc[i][0] = fmaf(av[i], bv.x, acc[i][0]);
            acc[i][1] = fmaf(av[i], bv.y, acc[i][1]);
            acc[i][2] = fmaf(av[i], bv.z, acc[i][2]);
            acc[i][3] = fmaf(av[i], bv.w, acc[i][3]);
        }
    }
    #pragma unroll
    for (int i = 0; i < 4; i++) {
        int row = row0 + ty*4 + i;
        if (row < NATOMS) {
            float4 o;
            o.x = acc[i][0] + sB[tx*4+0];
            o.y = acc[i][1] + sB[tx*4+1];
            o.z = acc[i][2] + sB[tx*4+2];
            o.w = acc[i][3] + sB[tx*4+3];
            *(float4*)(g_x + row*64 + (tx << 2)) = o;
        }
    }
}

// =============== gather: s[n,f] = sum_m w0[l][n,m] * x[nbr[n,m], f] ==========
__global__ void gather_kernel(const int* __restrict__ nbr_idx, int l)
{
    const int tid = threadIdx.x;
    if (blockIdx.x == 0 && tid < 2*FDIM) g_bnsum[tid] = 0.0f;   // used only by later kernels
    const int n = blockIdx.x*4 + (tid >> 6);
    const int f = tid & 63;
    if (n >= NATOMS) return;
    const int*   ip = nbr_idx + n*MNBR;
    const float* wp = g_w0 + l*NEDGE + n*MNBR;
    float acc = 0.0f;
    #pragma unroll
    for (int m = 0; m < MNBR; m++) {
        acc = fmaf(wp[m], g_x[ip[m]*64 + f], acc);
    }
    g_s[n*64 + f] = acc;
}

// =============== conv: y = x + s @ (tpW * TP_NORM) ===========================
__global__ __launch_bounds__(256) void conv_kernel(const float* __restrict__ tpW, int l)
{
    __shared__ float sS[64*65];
    __shared__ float sW[64*64];
    const int tid = threadIdx.x;
    const int row0 = blockIdx.x * 64;
    for (int i = tid; i < 64*64; i += 256) {
        int r = i >> 6, k = i & 63;
        int row = row0 + r;
        sS[r*65 + k] = (row < NATOMS) ? g_s[row*64 + k] : 0.0f;
        sW[i] = tpW[l*4096 + i] * TPN;
    }
    __syncthreads();
    const int tx = tid & 15, ty = tid >> 4;
    float acc[4][4];
    #pragma unroll
    for (int i = 0; i < 4; i++)
        #pragma unroll
        for (int j = 0; j < 4; j++) acc[i][j] = 0.0f;
    #pragma unroll 4
    for (int k = 0; k < 64; k++) {
        float4 bv = *(const float4*)(sW + k*64 + (tx << 2));
        float av[4];
        #pragma unroll
        for (int i = 0; i < 4; i++) av[i] = sS[(ty*4 + i)*65 + k];
        #pragma unroll
        for (int i = 0; i < 4; i++) {
            acc[i][0] = fmaf(av[i], bv.x, acc[i][0]);
            acc[i][1] = fmaf(av[i], bv.y, acc[i][1]);
            acc[i][2] = fmaf(av[i], bv.z, acc[i][2]);
            acc[i][3] = fmaf(av[i], bv.w, acc[i][3]);
        }
    }
    #pragma unroll
    for (int i = 0; i < 4; i++) {
        int row = row0 + ty*4 + i;
        if (row < NATOMS) {
            float4 xv = *(const float4*)(g_x + row*64 + (tx << 2));
            float4 o;
            o.x = xv.x + acc[i][0];
            o.y = xv.y + acc[i][1];
            o.z = xv.z + acc[i][2];
            o.w = xv.w + acc[i][3];
            *(float4*)(g_y + row*64 + (tx << 2)) = o;
        }
    }
}

// =============== BN batch statistics ========================================
__global__ void stats_kernel()
{
    __shared__ float ss[128];
    const int tid = threadIdx.x;  // 256
    if (tid < 128) ss[tid] = 0.0f;
    __syncthreads();
    float s = 0.0f, q = 0.0f;
    const int c = (blockIdx.x*256 + tid) & 63;  // stride is multiple of 64 -> c constant
    for (int i = blockIdx.x*256 + tid; i < NATOMS*FDIM; i += gridDim.x*256) {
        float v = g_y[i];
        s += v; q = fmaf(v, v, q);
    }
    atomicAdd(&ss[c], s);
    atomicAdd(&ss[64 + c], q);
    __syncthreads();
    if (tid < 128) atomicAdd(&g_bnsum[tid], ss[tid]);
}

// =============== BN apply + softplus -> new x ================================
__global__ void bn_kernel(const float* __restrict__ gamma, const float* __restrict__ beta, int l)
{
    __shared__ float ssc[64], ssh[64];
    const int tid = threadIdx.x;  // 256
    if (tid < 64) {
        float mu  = g_bnsum[tid] * (1.0f/NATOMS);
        float var = g_bnsum[64 + tid] * (1.0f/NATOMS) - mu*mu;
        float sc  = gamma[l*64 + tid] * rsqrtf(var + EPSB);
        ssc[tid] = sc;
        ssh[tid] = beta[l*64 + tid] - mu*sc;
    }
    __syncthreads();
    const int total4 = NATOMS*FDIM/4;
    for (int i = blockIdx.x*256 + tid; i < total4; i += gridDim.x*256) {
        float4 v = ((const float4*)g_y)[i];
        int c = (i & 15) << 2;
        v.x = softplus_f(fmaf(ssc[c+0], v.x, ssh[c+0]));
        v.y = softplus_f(fmaf(ssc[c+1], v.y, ssh[c+1]));
        v.z = softplus_f(fmaf(ssc[c+2], v.z, ssh[c+2]));
        v.w = softplus_f(fmaf(ssc[c+3], v.w, ssh[c+3]));
        ((float4*)g_x)[i] = v;
    }
}

// =============== pooling + MLP head =========================================
// out layout: [ out(500) | h(500*128) ]
__global__ __launch_bounds__(128) void head_kernel(
    const int* __restrict__ cidx, const float* __restrict__ fcW, const float* __restrict__ fcb,
    const float* __restrict__ outW, const float* __restrict__ outb, float* __restrict__ out)
{
    __shared__ float spart[128];
    __shared__ float crys[64];
    __shared__ float hred[128];
    const int b = blockIdx.x, tid = threadIdx.x;
    const int f = tid & 63, half = tid >> 6;
    const int* ci = cidx + b*NPC + half*(NPC/2);
    float a = 0.0f;
    #pragma unroll 4
    for (int i = 0; i < NPC/2; i++) a += g_x[ci[i]*64 + f];
    spart[tid] = a;
    __syncthreads();
    if (tid < 64) crys[tid] = (spart[tid] + spart[tid + 64]) * (1.0f/NPC);
    __syncthreads();
    float acc = fcb[tid];
    #pragma unroll 8
    for (int k = 0; k < 64; k++) acc = fmaf(crys[k], fcW[k*128 + tid], acc);
    float h = softplus_f(acc);
    out[BQ + b*HFD + tid] = h;
    hred[tid] = h * outW[tid];
    __syncthreads();
    for (int sft = 64; sft > 0; sft >>= 1) {
        if (tid < sft) hred[tid] += hred[tid + sft];
        __syncthreads();
    }
    if (tid == 0) out[b] = hred[0] + outb[0];
}

// ============================================================================
extern "C" void kernel_launch(void* const* d_in, const int* in_sizes, int n_in,
                              void* d_out, int out_size)
{
    const float* atom_fea = (const float*)d_in[0];
    const float* nbr_fea  = (const float*)d_in[1];
    /* d_in[2] = pos (unused: only Y_0 path contributes) */
    const float* emb_W    = (const float*)d_in[3];
    const float* emb_b    = (const float*)d_in[4];
    const float* rW1      = (const float*)d_in[5];
    const float* rb1      = (const float*)d_in[6];
    const float* rW2      = (const float*)d_in[7];
    const float* rb2      = (const float*)d_in[8];
    const float* tpW      = (const float*)d_in[9];
    const float* bn_gamma = (const float*)d_in[10];
    const float* bn_beta  = (const float*)d_in[11];
    const float* fc_W     = (const float*)d_in[12];
    const float* fc_b     = (const float*)d_in[13];
    const float* out_W    = (const float*)d_in[14];
    const float* out_b    = (const float*)d_in[15];
    const int*   nbr_idx  = (const int*)d_in[16];
    const int*   cidx     = (const int*)d_in[17];
    float* out = (float*)d_out;

    const int edge_smem = (41*123 + 123 + 123)*(int)sizeof(float2) + EPB*NBRD*(int)sizeof(float);
    cudaFuncSetAttribute(edge_kernel, cudaFuncAttributeMaxDynamicSharedMemorySize, edge_smem);

    embed_kernel<<<(NATOMS + 63)/64, 256>>>(atom_fea, emb_W, emb_b);
    edge_kernel<<<(NEDGE + EPB - 1)/EPB, 128, edge_smem>>>(nbr_fea, rW1, rb1, rW2, rb2);
    for (int l = 0; l < NCONVL; l++) {
        gather_kernel<<<(NATOMS + 3)/4, 256>>>(nbr_idx, l);
        conv_kernel<<<(NATOMS + 63)/64, 256>>>(tpW, l);
        stats_kernel<<<592, 256>>>();
        bn_kernel<<<592, 256>>>(bn_gamma, bn_beta, l);
    }
    head_kernel<<<BQ, 128>>>(cidx, fc_W, fc_b, out_W, out_b, out);
}

// round 3
// speedup vs baseline: 1.2382x; 1.2382x over previous
#include <cuda_runtime.h>
#include <math.h>

#define NATOMS 100000
#define MNBR   12
#define NEDGE  (NATOMS*MNBR)
#define ORIG   92
#define NBRD   41
#define FDIM   64
#define HFD    128
#define NCONVL 3
#define BQ     500
#define NPC    200
#define Y0C    0.28209479177387814f
#define TPN    0.125f
#define EPSB   1e-5f

// ---------------- scratch (no cudaMalloc allowed) ----------------
__device__ float g_x[NATOMS*FDIM];
__device__ float g_s[NATOMS*FDIM];
__device__ float g_y[NATOMS*FDIM];
__device__ float g_w0[3*NEDGE];
__device__ float g_bnsum[2*FDIM];

__device__ __forceinline__ float softplus_f(float z) {
    float t = fabsf(z);
    float e = __expf(-t);
    return fmaxf(z, 0.0f) + __logf(1.0f + e);
}

#define FFMA2(acc, w, x) asm("fma.rn.f32x2 %0, %1, %2, %3;" : "=l"(acc) : "l"(w), "l"(x), "l"(acc))
#define PACK2(d, a, b)   asm("mov.b64 %0, {%1, %2};" : "=l"(d) : "f"(a), "f"(b))
#define SPLAT2(d, a)     asm("mov.b64 %0, {%1, %1};" : "=l"(d) : "f"(a))
#define UNPACK2(a, b, d) asm("mov.b64 {%0, %1}, %2;" : "=f"(a), "=f"(b) : "l"(d))

// =============== fused 3-layer edge kernel =====================
// w0[l][e] = Y0/M * ( sum_j softplus( nbr[e]·rW1[l][:,j] + rb1[l][j] ) * rW2[l][j,0] + rb2[l][0] )
// 4 edges per thread: two f32x2 pairs share each weight LDS.64.
#define EPB 512
__global__ __launch_bounds__(128, 2) void edge_kernel(
    const float* __restrict__ nbr_fea, const float* __restrict__ rW1,
    const float* __restrict__ rb1, const float* __restrict__ rW2,
    const float* __restrict__ rb2)
{
    extern __shared__ float smf[];
    float2* sWd  = (float2*)smf;          // [41][123] duplicated: sWd[k*123+col]
    float2* sb1d = sWd + 41*123;          // [123]
    float2* sw2d = sb1d + 123;            // [123]  (rW2 col0 * Y0/M, duplicated)
    float*  sIn  = (float*)(sw2d + 123);  // [256][41] chunk staging (reused)
    const int tid = threadIdx.x;

    for (int i = tid; i < 41*123; i += 128) {
        int k = i / 123, j = i % 123;
        int l = j / 41, jj = j % 41;
        float w = rW1[(l*41 + k)*41 + jj];
        sWd[i] = make_float2(w, w);
    }
    for (int i = tid; i < 123; i += 128) {
        float b = rb1[i];
        sb1d[i] = make_float2(b, b);
        int l = i / 41, jj = i % 41;
        float w2 = rW2[(l*41 + jj)*9] * (Y0C / (float)MNBR);
        sw2d[i] = make_float2(w2, w2);
    }

    const int base = blockIdx.x * EPB;

    // ---- stage chunk 0 (edges [base, base+256)), pack to regs ----
    for (int i = tid; i < 256*NBRD; i += 128) {
        int g = base*NBRD + i;
        sIn[i] = (g < NEDGE*NBRD) ? nbr_fea[g] : 0.0f;
    }
    __syncthreads();
    unsigned long long Av[41];
    #pragma unroll
    for (int k = 0; k < 41; k++)
        PACK2(Av[k], sIn[tid*41 + k], sIn[(tid + 128)*41 + k]);
    __syncthreads();

    // ---- stage chunk 1 (edges [base+256, base+512)), pack to regs ----
    for (int i = tid; i < 256*NBRD; i += 128) {
        int g = (base + 256)*NBRD + i;
        sIn[i] = (g < NEDGE*NBRD) ? nbr_fea[g] : 0.0f;
    }
    __syncthreads();
    unsigned long long Bv[41];
    #pragma unroll
    for (int k = 0; k < 41; k++)
        PACK2(Bv[k], sIn[tid*41 + k], sIn[(tid + 128)*41 + k]);

    const int eA0 = base + tid;           // always valid (grid covers NEDGE)
    const int eA1 = eA0 + 128;
    const int eB0 = base + 256 + tid;
    const int eB1 = eB0 + 128;

    for (int l = 0; l < 3; l++) {
        unsigned long long waccA = 0ULL, waccB = 0ULL;
        const float r0 = rb2[l*9] * (Y0C / (float)MNBR);
        for (int j = 0; j < 41; j++) {
            const int col = l*41 + j;
            unsigned long long accA = *(const unsigned long long*)(sb1d + col);
            unsigned long long accB = accA;
            const unsigned long long* wrow = ((const unsigned long long*)sWd) + col;
            #pragma unroll
            for (int k = 0; k < 41; k++) {
                unsigned long long w = wrow[k*123];
                FFMA2(accA, w, Av[k]);
                FFMA2(accB, w, Bv[k]);
            }
            float za0, za1, zb0, zb1;
            UNPACK2(za0, za1, accA);
            UNPACK2(zb0, zb1, accB);
            unsigned long long spA, spB;
            PACK2(spA, softplus_f(za0), softplus_f(za1));
            PACK2(spB, softplus_f(zb0), softplus_f(zb1));
            unsigned long long w2 = *((const unsigned long long*)(sw2d + col));
            FFMA2(waccA, w2, spA);
            FFMA2(waccB, w2, spB);
        }
        float a0, a1, b0, b1;
        UNPACK2(a0, a1, waccA);
        UNPACK2(b0, b1, waccB);
        float* wout = g_w0 + l*NEDGE;
        wout[eA0] = a0 + r0;
        if (eA1 < NEDGE) wout[eA1] = a1 + r0;
        if (eB0 < NEDGE) wout[eB0] = b0 + r0;
        if (eB1 < NEDGE) wout[eB1] = b1 + r0;
    }
}

// =============== embedding: x = atom_fea @ emb_W + emb_b (f32x2) =============
__global__ __launch_bounds__(256) void embed_kernel(
    const float* __restrict__ A, const float* __restrict__ W, const float* __restrict__ bias)
{
    __shared__ float sA[64*93];
    __shared__ __align__(16) float sW[92*64];
    __shared__ float sB[64];
    const int tid = threadIdx.x;
    const int row0 = blockIdx.x * 64;
    for (int i = tid; i < 64*92; i += 256) {
        int r = i / 92, k = i % 92;
        int row = row0 + r;
        sA[r*93 + k] = (row < NATOMS) ? A[row*92 + k] : 0.0f;
    }
    for (int i = tid; i < 92*64; i += 256) sW[i] = W[i];
    if (tid < 64) sB[tid] = bias[tid];
    __syncthreads();
    const int tx = tid & 15, ty = tid >> 4;
    unsigned long long acc[4][2];
    #pragma unroll
    for (int i = 0; i < 4; i++) { acc[i][0] = 0ULL; acc[i][1] = 0ULL; }
    #pragma unroll 4
    for (int k = 0; k < 92; k++) {
        ulonglong2 wv = *(const ulonglong2*)(sW + k*64 + (tx << 2));
        #pragma unroll
        for (int i = 0; i < 4; i++) {
            float a = sA[(ty*4 + i)*93 + k];
            unsigned long long a2; SPLAT2(a2, a);
            FFMA2(acc[i][0], wv.x, a2);
            FFMA2(acc[i][1], wv.y, a2);
        }
    }
    #pragma unroll
    for (int i = 0; i < 4; i++) {
        int row = row0 + ty*4 + i;
        if (row < NATOMS) {
            float4 o;
            UNPACK2(o.x, o.y, acc[i][0]);
            UNPACK2(o.z, o.w, acc[i][1]);
            o.x += sB[tx*4+0]; o.y += sB[tx*4+1];
            o.z += sB[tx*4+2]; o.w += sB[tx*4+3];
            *(float4*)(g_x + row*64 + (tx << 2)) = o;
        }
    }
}

// =============== gather: s[n,f] = sum_m w0[l][n,m] * x[nbr[n,m], f] ==========
__global__ void gather_kernel(const int* __restrict__ nbr_idx, int l)
{
    const int tid = threadIdx.x;
    if (blockIdx.x == 0 && tid < 2*FDIM) g_bnsum[tid] = 0.0f;   // used only by later kernels
    const int n = blockIdx.x*4 + (tid >> 6);
    const int f = tid & 63;
    if (n >= NATOMS) return;
    const int*   ip = nbr_idx + n*MNBR;
    const float* wp = g_w0 + l*NEDGE + n*MNBR;
    float acc = 0.0f;
    #pragma unroll
    for (int m = 0; m < MNBR; m++) {
        acc = fmaf(wp[m], g_x[ip[m]*64 + f], acc);
    }
    g_s[n*64 + f] = acc;
}

// =============== conv: y = x + s @ (tpW * TP_NORM) (f32x2) ===================
__global__ __launch_bounds__(256) void conv_kernel(const float* __restrict__ tpW, int l)
{
    __shared__ float sS[64*65];
    __shared__ __align__(16) float sW[64*64];
    const int tid = threadIdx.x;
    const int row0 = blockIdx.x * 64;
    for (int i = tid; i < 64*64; i += 256) {
        int r = i >> 6, k = i & 63;
        int row = row0 + r;
        sS[r*65 + k] = (row < NATOMS) ? g_s[row*64 + k] : 0.0f;
        sW[i] = tpW[l*4096 + i] * TPN;
    }
    __syncthreads();
    const int tx = tid & 15, ty = tid >> 4;
    unsigned long long acc[4][2];
    #pragma unroll
    for (int i = 0; i < 4; i++) { acc[i][0] = 0ULL; acc[i][1] = 0ULL; }
    #pragma unroll 4
    for (int k = 0; k < 64; k++) {
        ulonglong2 wv = *(const ulonglong2*)(sW + k*64 + (tx << 2));
        #pragma unroll
        for (int i = 0; i < 4; i++) {
            float a = sS[(ty*4 + i)*65 + k];
            unsigned long long a2; SPLAT2(a2, a);
            FFMA2(acc[i][0], wv.x, a2);
            FFMA2(acc[i][1], wv.y, a2);
        }
    }
    #pragma unroll
    for (int i = 0; i < 4; i++) {
        int row = row0 + ty*4 + i;
        if (row < NATOMS) {
            float4 xv = *(const float4*)(g_x + row*64 + (tx << 2));
            float4 o;
            UNPACK2(o.x, o.y, acc[i][0]);
            UNPACK2(o.z, o.w, acc[i][1]);
            o.x += xv.x; o.y += xv.y; o.z += xv.z; o.w += xv.w;
            *(float4*)(g_y + row*64 + (tx << 2)) = o;
        }
    }
}

// =============== BN batch statistics ========================================
__global__ void stats_kernel()
{
    __shared__ float ss[128];
    const int tid = threadIdx.x;  // 256
    if (tid < 128) ss[tid] = 0.0f;
    __syncthreads();
    float s = 0.0f, q = 0.0f;
    const int c = (blockIdx.x*256 + tid) & 63;  // stride is multiple of 64 -> c constant
    for (int i = blockIdx.x*256 + tid; i < NATOMS*FDIM; i += gridDim.x*256) {
        float v = g_y[i];
        s += v; q = fmaf(v, v, q);
    }
    atomicAdd(&ss[c], s);
    atomicAdd(&ss[64 + c], q);
    __syncthreads();
    if (tid < 128) atomicAdd(&g_bnsum[tid], ss[tid]);
}

// =============== BN apply + softplus -> new x ================================
__global__ void bn_kernel(const float* __restrict__ gamma, const float* __restrict__ beta, int l)
{
    __shared__ float ssc[64], ssh[64];
    const int tid = threadIdx.x;  // 256
    if (tid < 64) {
        float mu  = g_bnsum[tid] * (1.0f/NATOMS);
        float var = g_bnsum[64 + tid] * (1.0f/NATOMS) - mu*mu;
        float sc  = gamma[l*64 + tid] * rsqrtf(var + EPSB);
        ssc[tid] = sc;
        ssh[tid] = beta[l*64 + tid] - mu*sc;
    }
    __syncthreads();
    const int total4 = NATOMS*FDIM/4;
    for (int i = blockIdx.x*256 + tid; i < total4; i += gridDim.x*256) {
        float4 v = ((const float4*)g_y)[i];
        int c = (i & 15) << 2;
        v.x = softplus_f(fmaf(ssc[c+0], v.x, ssh[c+0]));
        v.y = softplus_f(fmaf(ssc[c+1], v.y, ssh[c+1]));
        v.z = softplus_f(fmaf(ssc[c+2], v.z, ssh[c+2]));
        v.w = softplus_f(fmaf(ssc[c+3], v.w, ssh[c+3]));
        ((float4*)g_x)[i] = v;
    }
}

// =============== pooling + MLP head =========================================
// out layout: [ out(500) | h(500*128) ]
__global__ __launch_bounds__(128) void head_kernel(
    const int* __restrict__ cidx, const float* __restrict__ fcW, const float* __restrict__ fcb,
    const float* __restrict__ outW, const float* __restrict__ outb, float* __restrict__ out)
{
    __shared__ float spart[128];
    __shared__ float crys[64];
    __shared__ float hred[128];
    const int b = blockIdx.x, tid = threadIdx.x;
    const int f = tid & 63, half = tid >> 6;
    const int* ci = cidx + b*NPC + half*(NPC/2);
    float a = 0.0f;
    #pragma unroll 4
    for (int i = 0; i < NPC/2; i++) a += g_x[ci[i]*64 + f];
    spart[tid] = a;
    __syncthreads();
    if (tid < 64) crys[tid] = (spart[tid] + spart[tid + 64]) * (1.0f/NPC);
    __syncthreads();
    float acc = fcb[tid];
    #pragma unroll 8
    for (int k = 0; k < 64; k++) acc = fmaf(crys[k], fcW[k*128 + tid], acc);
    float h = softplus_f(acc);
    out[BQ + b*HFD + tid] = h;
    hred[tid] = h * outW[tid];
    __syncthreads();
    for (int sft = 64; sft > 0; sft >>= 1) {
        if (tid < sft) hred[tid] += hred[tid + sft];
        __syncthreads();
    }
    if (tid == 0) out[b] = hred[0] + outb[0];
}

// ============================================================================
extern "C" void kernel_launch(void* const* d_in, const int* in_sizes, int n_in,
                              void* d_out, int out_size)
{
    const float* atom_fea = (const float*)d_in[0];
    const float* nbr_fea  = (const float*)d_in[1];
    /* d_in[2] = pos (unused: only Y_0 path contributes) */
    const float* emb_W    = (const float*)d_in[3];
    const float* emb_b    = (const float*)d_in[4];
    const float* rW1      = (const float*)d_in[5];
    const float* rb1      = (const float*)d_in[6];
    const float* rW2      = (const float*)d_in[7];
    const float* rb2      = (const float*)d_in[8];
    const float* tpW      = (const float*)d_in[9];
    const float* bn_gamma = (const float*)d_in[10];
    const float* bn_beta  = (const float*)d_in[11];
    const float* fc_W     = (const float*)d_in[12];
    const float* fc_b     = (const float*)d_in[13];
    const float* out_W    = (const float*)d_in[14];
    const float* out_b    = (const float*)d_in[15];
    const int*   nbr_idx  = (const int*)d_in[16];
    const int*   cidx     = (const int*)d_in[17];
    float* out = (float*)d_out;

    const int edge_smem = (41*123 + 123 + 123)*(int)sizeof(float2) + 256*NBRD*(int)sizeof(float);
    cudaFuncSetAttribute(edge_kernel, cudaFuncAttributeMaxDynamicSharedMemorySize, edge_smem);

    embed_kernel<<<(NATOMS + 63)/64, 256>>>(atom_fea, emb_W, emb_b);
    edge_kernel<<<(NEDGE + EPB - 1)/EPB, 128, edge_smem>>>(nbr_fea, rW1, rb1, rW2, rb2);
    for (int l = 0; l < NCONVL; l++) {
        gather_kernel<<<(NATOMS + 3)/4, 256>>>(nbr_idx, l);
        conv_kernel<<<(NATOMS + 63)/64, 256>>>(tpW, l);
        stats_kernel<<<592, 256>>>();
        bn_kernel<<<592, 256>>>(bn_gamma, bn_beta, l);
    }
    head_kernel<<<BQ, 128>>>(cidx, fc_W, fc_b, out_W, out_b, out);
}

// round 5
// speedup vs baseline: 1.7004x; 1.3733x over previous
#include <cuda_runtime.h>
#include <math.h>
#include <stdint.h>

#define NATOMS 100000
#define MNBR   12
#define NEDGE  (NATOMS*MNBR)
#define ORIG   92
#define NBRD   41
#define FDIM   64
#define HFD    128
#define NCONVL 3
#define BQ     500
#define NPC    200
#define Y0C    0.28209479177387814f
#define TPN    0.125f
#define EPSB   1e-5f

// ---------------- scratch (no cudaMalloc allowed) ----------------
__device__ float g_x[NATOMS*FDIM];
__device__ float g_s[NATOMS*FDIM];
__device__ float g_y[NATOMS*FDIM];
__device__ float g_w0[3*NEDGE];
__device__ float g_bnsum[2*FDIM];
__device__ float g_Wpad[48*128];    // tf32-truncated, K-major [48][128]
__device__ float g_epib1[128];
__device__ float g_epiw2[128];
__device__ float g_epir0[3];

__device__ __forceinline__ float softplus_f(float z) {
    float t = fabsf(z);
    float e = __expf(-t);
    return fmaxf(z, 0.0f) + __logf(1.0f + e);
}

#define FFMA2(acc, w, x) asm("fma.rn.f32x2 %0, %1, %2, %3;" : "=l"(acc) : "l"(w), "l"(x), "l"(acc))
#define SPLAT2(d, a)     asm("mov.b64 %0, {%1, %1};" : "=l"(d) : "f"(a))
#define UNPACK2(a, b, d) asm("mov.b64 {%0, %1}, %2;" : "=f"(a), "=f"(b) : "l"(d))

__device__ __forceinline__ uint32_t to_tf32(float v) {
    uint32_t t;
    asm("cvt.rna.tf32.f32 %0, %1;" : "=r"(t) : "f"(v));
    return t;
}

__device__ __forceinline__ void mma_tf32(float& d0, float& d1, float& d2, float& d3,
                                         uint32_t a0, uint32_t a1, uint32_t a2, uint32_t a3,
                                         uint32_t b0, uint32_t b1) {
    asm volatile("mma.sync.aligned.m16n8k8.row.col.f32.tf32.tf32.f32 "
                 "{%0,%1,%2,%3}, {%4,%5,%6,%7}, {%8,%9}, {%0,%1,%2,%3};"
                 : "+f"(d0), "+f"(d1), "+f"(d2), "+f"(d3)
                 : "r"(a0), "r"(a1), "r"(a2), "r"(a3), "r"(b0), "r"(b1));
}

// ============ setup: padded tf32 W image + epilogue constants ============
__global__ void setup_kernel(const float* __restrict__ rW1, const float* __restrict__ rb1,
                             const float* __restrict__ rW2, const float* __restrict__ rb2)
{
    const int tid = threadIdx.x;   // 256
    // Wpad[k][j] = rW1[l][k][jj], j = l*41+jj; zero pad k>=41 or j>=123
    for (int i = tid; i < 48*128; i += 256) {
        int k = i >> 7, j = i & 127;
        float v = 0.0f;
        if (k < 41 && j < 123) {
            int l = j / 41, jj = j - l*41;
            v = rW1[(l*41 + k)*41 + jj];
        }
        g_Wpad[i] = __uint_as_float(to_tf32(v));
    }
    if (tid < 128) {
        float b1 = 0.0f, w2 = 0.0f;
        if (tid < 123) {
            int l = tid / 41, jj = tid - l*41;
            b1 = rb1[l*41 + jj];
            w2 = rW2[(l*41 + jj)*9] * (Y0C / (float)MNBR);
        }
        g_epib1[tid] = b1;
        g_epiw2[tid] = w2;
    }
    if (tid < 3) g_epir0[tid] = rb2[tid*9] * (Y0C / (float)MNBR);
}

// ============ edge kernel: mma.sync tf32, 64 edges per CTA ====================
// Z[64x128] = A[64x48] @ Wpad[48x128]; then softplus+dot epilogue -> g_w0[3][edge].
__global__ __launch_bounds__(128, 3) void edge_mma_kernel(const float* __restrict__ nbr_fea)
{
    __shared__ float sA[64*52];          // stride 52: conflict-free A-frag LDS
    __shared__ float sRed[4][64*3];      // per-warp partials [warp][row*3+layer]
    const int tid  = threadIdx.x;
    const int wid  = tid >> 5, lane = tid & 31;
    const int g    = lane >> 2, q = lane & 3;
    const int base = blockIdx.x * 64;

    // ---- stage A (tf32-truncated), pad K 41->48 with zeros ----
    const float* src = nbr_fea + (size_t)base * NBRD;
    for (int i = tid; i < 64*NBRD; i += 128) {
        int r = i / NBRD, c = i - r*NBRD;
        sA[r*52 + c] = __uint_as_float(to_tf32(src[i]));
    }
    for (int i = tid; i < 64*7; i += 128) {
        int r = i / 7, c = 41 + (i - r*7);
        sA[r*52 + c] = 0.0f;
    }

    // ---- preload B fragments (48 regs) + epilogue constants ----
    const int wbase = wid * 32;
    uint32_t bf[6][4][2];
    #pragma unroll
    for (int k = 0; k < 6; k++)
        #pragma unroll
        for (int nt = 0; nt < 4; nt++) {
            int col = wbase + nt*8 + g;
            bf[k][nt][0] = __float_as_uint(g_Wpad[(k*8 + q)*128 + col]);
            bf[k][nt][1] = __float_as_uint(g_Wpad[(k*8 + q + 4)*128 + col]);
        }
    float b1a[4], b1b[4], w2a[4], w2b[4];
    int lyA[4], lyB[4];
    #pragma unroll
    for (int nt = 0; nt < 4; nt++) {
        int ja = wbase + nt*8 + q*2, jb = ja + 1;
        b1a[nt] = g_epib1[ja]; b1b[nt] = g_epib1[jb];
        w2a[nt] = g_epiw2[ja]; w2b[nt] = g_epiw2[jb];
        lyA[nt] = (ja < 41) ? 0 : ((ja < 82) ? 1 : 2);
        lyB[nt] = (jb < 41) ? 0 : ((jb < 82) ? 1 : 2);
    }
    __syncthreads();

    #pragma unroll
    for (int m = 0; m < 4; m++) {
        float d[4][4];
        #pragma unroll
        for (int nt = 0; nt < 4; nt++)
            #pragma unroll
            for (int f = 0; f < 4; f++) d[nt][f] = 0.0f;

        const int row0 = m*16 + g, row1 = row0 + 8;
        #pragma unroll
        for (int k = 0; k < 6; k++) {
            uint32_t a0 = __float_as_uint(sA[row0*52 + k*8 + q]);
            uint32_t a1 = __float_as_uint(sA[row1*52 + k*8 + q]);
            uint32_t a2 = __float_as_uint(sA[row0*52 + k*8 + q + 4]);
            uint32_t a3 = __float_as_uint(sA[row1*52 + k*8 + q + 4]);
            #pragma unroll
            for (int nt = 0; nt < 4; nt++)
                mma_tf32(d[nt][0], d[nt][1], d[nt][2], d[nt][3],
                         a0, a1, a2, a3, bf[k][nt][0], bf[k][nt][1]);
        }

        // ---- epilogue for this m-tile ----
        float aA0 = 0.0f, aA1 = 0.0f, aA2 = 0.0f;   // row0 accumulators per layer
        float aB0 = 0.0f, aB1 = 0.0f, aB2 = 0.0f;   // row1
        #pragma unroll
        for (int nt = 0; nt < 4; nt++) {
            float v00 = softplus_f(d[nt][0] + b1a[nt]) * w2a[nt];  // row0, ja
            float v01 = softplus_f(d[nt][1] + b1b[nt]) * w2b[nt];  // row0, jb
            float v10 = softplus_f(d[nt][2] + b1a[nt]) * w2a[nt];  // row1, ja
            float v11 = softplus_f(d[nt][3] + b1b[nt]) * w2b[nt];  // row1, jb
            if (lyA[nt] == 0) { aA0 += v00; aB0 += v10; }
            else if (lyA[nt] == 1) { aA1 += v00; aB1 += v10; }
            else { aA2 += v00; aB2 += v10; }
            if (lyB[nt] == 0) { aA0 += v01; aB0 += v11; }
            else if (lyB[nt] == 1) { aA1 += v01; aB1 += v11; }
            else { aA2 += v01; aB2 += v11; }
        }
        // quad reduction (lanes q=0..3 share rows)
        #pragma unroll
        for (int s = 1; s <= 2; s <<= 1) {
            aA0 += __shfl_xor_sync(0xffffffffu, aA0, s);
            aA1 += __shfl_xor_sync(0xffffffffu, aA1, s);
            aA2 += __shfl_xor_sync(0xffffffffu, aA2, s);
            aB0 += __shfl_xor_sync(0xffffffffu, aB0, s);
            aB1 += __shfl_xor_sync(0xffffffffu, aB1, s);
            aB2 += __shfl_xor_sync(0xffffffffu, aB2, s);
        }
        if (q == 0) {
            sRed[wid][row0*3 + 0] = aA0;
            sRed[wid][row0*3 + 1] = aA1;
            sRed[wid][row0*3 + 2] = aA2;
            sRed[wid][row1*3 + 0] = aB0;
            sRed[wid][row1*3 + 1] = aB1;
            sRed[wid][row1*3 + 2] = aB2;
        }
    }
    __syncthreads();

    // ---- cross-warp combine + write ----
    for (int i = tid; i < 64*3; i += 128) {
        int row = i / 3, ly = i - row*3;
        float s = sRed[0][i] + sRed[1][i] + sRed[2][i] + sRed[3][i];
        g_w0[ly*NEDGE + base + row] = s + g_epir0[ly];
    }
}

// =============== embedding: x = atom_fea @ emb_W + emb_b (f32x2) =============
__global__ __launch_bounds__(256) void embed_kernel(
    const float* __restrict__ A, const float* __restrict__ W, const float* __restrict__ bias)
{
    __shared__ float sA[64*93];
    __shared__ __align__(16) float sW[92*64];
    __shared__ float sB[64];
    const int tid = threadIdx.x;
    const int row0 = blockIdx.x * 64;
    for (int i = tid; i < 64*92; i += 256) {
        int r = i / 92, k = i % 92;
        int row = row0 + r;
        sA[r*93 + k] = (row < NATOMS) ? A[row*92 + k] : 0.0f;
    }
    for (int i = tid; i < 92*64; i += 256) sW[i] = W[i];
    if (tid < 64) sB[tid] = bias[tid];
    __syncthreads();
    const int tx = tid & 15, ty = tid >> 4;
    unsigned long long acc[4][2];
    #pragma unroll
    for (int i = 0; i < 4; i++) { acc[i][0] = 0ULL; acc[i][1] = 0ULL; }
    #pragma unroll 4
    for (int k = 0; k < 92; k++) {
        ulonglong2 wv = *(const ulonglong2*)(sW + k*64 + (tx << 2));
        #pragma unroll
        for (int i = 0; i < 4; i++) {
            float a = sA[(ty*4 + i)*93 + k];
            unsigned long long a2; SPLAT2(a2, a);
            FFMA2(acc[i][0], wv.x, a2);
            FFMA2(acc[i][1], wv.y, a2);
        }
    }
    #pragma unroll
    for (int i = 0; i < 4; i++) {
        int row = row0 + ty*4 + i;
        if (row < NATOMS) {
            float4 o;
            UNPACK2(o.x, o.y, acc[i][0]);
            UNPACK2(o.z, o.w, acc[i][1]);
            o.x += sB[tx*4+0]; o.y += sB[tx*4+1];
            o.z += sB[tx*4+2]; o.w += sB[tx*4+3];
            *(float4*)(g_x + row*64 + (tx << 2)) = o;
        }
    }
}

// =============== gather: s[n,f] = sum_m w0[l][n,m] * x[nbr[n,m], f] ==========
__global__ void gather_kernel(const int* __restrict__ nbr_idx, int l)
{
    const int tid = threadIdx.x;
    if (blockIdx.x == 0 && tid < 2*FDIM) g_bnsum[tid] = 0.0f;
    const int n = blockIdx.x*4 + (tid >> 6);
    const int f = tid & 63;
    if (n >= NATOMS) return;
    const int*   ip = nbr_idx + n*MNBR;
    const float* wp = g_w0 + l*NEDGE + n*MNBR;
    float acc = 0.0f;
    #pragma unroll
    for (int m = 0; m < MNBR; m++) {
        acc = fmaf(wp[m], g_x[ip[m]*64 + f], acc);
    }
    g_s[n*64 + f] = acc;
}

// =============== conv: y = x + s @ (tpW * TP_NORM) (f32x2) ===================
__global__ __launch_bounds__(256) void conv_kernel(const float* __restrict__ tpW, int l)
{
    __shared__ float sS[64*65];
    __shared__ __align__(16) float sW[64*64];
    const int tid = threadIdx.x;
    const int row0 = blockIdx.x * 64;
    for (int i = tid; i < 64*64; i += 256) {
        int r = i >> 6, k = i & 63;
        int row = row0 + r;
        sS[r*65 + k] = (row < NATOMS) ? g_s[row*64 + k] : 0.0f;
        sW[i] = tpW[l*4096 + i] * TPN;
    }
    __syncthreads();
    const int tx = tid & 15, ty = tid >> 4;
    unsigned long long acc[4][2];
    #pragma unroll
    for (int i = 0; i < 4; i++) { acc[i][0] = 0ULL; acc[i][1] = 0ULL; }
    #pragma unroll 4
    for (int k = 0; k < 64; k++) {
        ulonglong2 wv = *(const ulonglong2*)(sW + k*64 + (tx << 2));
        #pragma unroll
        for (int i = 0; i < 4; i++) {
            float a = sS[(ty*4 + i)*65 + k];
            unsigned long long a2; SPLAT2(a2, a);
            FFMA2(acc[i][0], wv.x, a2);
            FFMA2(acc[i][1], wv.y, a2);
        }
    }
    #pragma unroll
    for (int i = 0; i < 4; i++) {
        int row = row0 + ty*4 + i;
        if (row < NATOMS) {
            float4 xv = *(const float4*)(g_x + row*64 + (tx << 2));
            float4 o;
            UNPACK2(o.x, o.y, acc[i][0]);
            UNPACK2(o.z, o.w, acc[i][1]);
            o.x += xv.x; o.y += xv.y; o.z += xv.z; o.w += xv.w;
            *(float4*)(g_y + row*64 + (tx << 2)) = o;
        }
    }
}

// =============== BN batch statistics ========================================
__global__ void stats_kernel()
{
    __shared__ float ss[128];
    const int tid = threadIdx.x;  // 256
    if (tid < 128) ss[tid] = 0.0f;
    __syncthreads();
    float s = 0.0f, q = 0.0f;
    const int c = (blockIdx.x*256 + tid) & 63;
    for (int i = blockIdx.x*256 + tid; i < NATOMS*FDIM; i += gridDim.x*256) {
        float v = g_y[i];
        s += v; q = fmaf(v, v, q);
    }
    atomicAdd(&ss[c], s);
    atomicAdd(&ss[64 + c], q);
    __syncthreads();
    if (tid < 128) atomicAdd(&g_bnsum[tid], ss[tid]);
}

// =============== BN apply + softplus -> new x ================================
__global__ void bn_kernel(const float* __restrict__ gamma, const float* __restrict__ beta, int l)
{
    __shared__ float ssc[64], ssh[64];
    const int tid = threadIdx.x;  // 256
    if (tid < 64) {
        float mu  = g_bnsum[tid] * (1.0f/NATOMS);
        float var = g_bnsum[64 + tid] * (1.0f/NATOMS) - mu*mu;
        float sc  = gamma[l*64 + tid] * rsqrtf(var + EPSB);
        ssc[tid] = sc;
        ssh[tid] = beta[l*64 + tid] - mu*sc;
    }
    __syncthreads();
    const int total4 = NATOMS*FDIM/4;
    for (int i = blockIdx.x*256 + tid; i < total4; i += gridDim.x*256) {
        float4 v = ((const float4*)g_y)[i];
        int c = (i & 15) << 2;
        v.x = softplus_f(fmaf(ssc[c+0], v.x, ssh[c+0]));
        v.y = softplus_f(fmaf(ssc[c+1], v.y, ssh[c+1]));
        v.z = softplus_f(fmaf(ssc[c+2], v.z, ssh[c+2]));
        v.w = softplus_f(fmaf(ssc[c+3], v.w, ssh[c+3]));
        ((float4*)g_x)[i] = v;
    }
}

// =============== pooling + MLP head =========================================
__global__ __launch_bounds__(128) void head_kernel(
    const int* __restrict__ cidx, const float* __restrict__ fcW, const float* __restrict__ fcb,
    const float* __restrict__ outW, const float* __restrict__ outb, float* __restrict__ out)
{
    __shared__ float spart[128];
    __shared__ float crys[64];
    __shared__ float hred[128];
    const int b = blockIdx.x, tid = threadIdx.x;
    const int f = tid & 63, half = tid >> 6;
    const int* ci = cidx + b*NPC + half*(NPC/2);
    float a = 0.0f;
    #pragma unroll 4
    for (int i = 0; i < NPC/2; i++) a += g_x[ci[i]*64 + f];
    spart[tid] = a;
    __syncthreads();
    if (tid < 64) crys[tid] = (spart[tid] + spart[tid + 64]) * (1.0f/NPC);
    __syncthreads();
    float acc = fcb[tid];
    #pragma unroll 8
    for (int k = 0; k < 64; k++) acc = fmaf(crys[k], fcW[k*128 + tid], acc);
    float h = softplus_f(acc);
    out[BQ + b*HFD + tid] = h;
    hred[tid] = h * outW[tid];
    __syncthreads();
    for (int sft = 64; sft > 0; sft >>= 1) {
        if (tid < sft) hred[tid] += hred[tid + sft];
        __syncthreads();
    }
    if (tid == 0) out[b] = hred[0] + outb[0];
}

// ============================================================================
extern "C" void kernel_launch(void* const* d_in, const int* in_sizes, int n_in,
                              void* d_out, int out_size)
{
    const float* atom_fea = (const float*)d_in[0];
    const float* nbr_fea  = (const float*)d_in[1];
    /* d_in[2] = pos (unused: only Y_0 path contributes) */
    const float* emb_W    = (const float*)d_in[3];
    const float* emb_b    = (const float*)d_in[4];
    const float* rW1      = (const float*)d_in[5];
    const float* rb1      = (const float*)d_in[6];
    const float* rW2      = (const float*)d_in[7];
    const float* rb2      = (const float*)d_in[8];
    const float* tpW      = (const float*)d_in[9];
    const float* bn_gamma = (const float*)d_in[10];
    const float* bn_beta  = (const float*)d_in[11];
    const float* fc_W     = (const float*)d_in[12];
    const float* fc_b     = (const float*)d_in[13];
    const float* out_W    = (const float*)d_in[14];
    const float* out_b    = (const float*)d_in[15];
    const int*   nbr_idx  = (const int*)d_in[16];
    const int*   cidx     = (const int*)d_in[17];
    float* out = (float*)d_out;

    setup_kernel<<<1, 256>>>(rW1, rb1, rW2, rb2);
    embed_kernel<<<(NATOMS + 63)/64, 256>>>(atom_fea, emb_W, emb_b);
    edge_mma_kernel<<<NEDGE/64, 128>>>(nbr_fea);
    for (int l = 0; l < NCONVL; l++) {
        gather_kernel<<<(NATOMS + 3)/4, 256>>>(nbr_idx, l);
        conv_kernel<<<(NATOMS + 63)/64, 256>>>(tpW, l);
        stats_kernel<<<592, 256>>>();
        bn_kernel<<<592, 256>>>(bn_gamma, bn_beta, l);
    }
    head_kernel<<<BQ, 128>>>(cidx, fc_W, fc_b, out_W, out_b, out);
}

// round 6
// speedup vs baseline: 1.7640x; 1.0374x over previous
#include <cuda_runtime.h>
#include <math.h>
#include <stdint.h>

#define NATOMS 100000
#define MNBR   12
#define NEDGE  (NATOMS*MNBR)
#define ORIG   92
#define NBRD   41
#define FDIM   64
#define HFD    128
#define NCONVL 3
#define BQ     500
#define NPC    200
#define Y0C    0.28209479177387814f
#define TPN    0.125f
#define EPSB   1e-5f

// ---------------- scratch (no cudaMalloc allowed) ----------------
__device__ float g_x[NATOMS*FDIM];
__device__ float g_y[NATOMS*FDIM];
__device__ float g_w0[3*NEDGE];
__device__ float g_bnsum[NCONVL*2*FDIM];   // [l][sum(64) | sumsq(64)]
__device__ float g_Wpad[48*128];           // tf32-truncated, K-major [48][128]
__device__ float g_epib1[128];
__device__ float g_epiw2[128];
__device__ float g_epir0[3];

__device__ __forceinline__ float softplus_f(float z) {
    float t = fabsf(z);
    float e = __expf(-t);
    return fmaxf(z, 0.0f) + __logf(1.0f + e);
}

#define FFMA2(acc, w, x) asm("fma.rn.f32x2 %0, %1, %2, %3;" : "=l"(acc) : "l"(w), "l"(x), "l"(acc))
#define SPLAT2(d, a)     asm("mov.b64 %0, {%1, %1};" : "=l"(d) : "f"(a))
#define UNPACK2(a, b, d) asm("mov.b64 {%0, %1}, %2;" : "=f"(a), "=f"(b) : "l"(d))

__device__ __forceinline__ uint32_t to_tf32(float v) {
    uint32_t t;
    asm("cvt.rna.tf32.f32 %0, %1;" : "=r"(t) : "f"(v));
    return t;
}

__device__ __forceinline__ void mma_tf32(float& d0, float& d1, float& d2, float& d3,
                                         uint32_t a0, uint32_t a1, uint32_t a2, uint32_t a3,
                                         uint32_t b0, uint32_t b1) {
    asm volatile("mma.sync.aligned.m16n8k8.row.col.f32.tf32.tf32.f32 "
                 "{%0,%1,%2,%3}, {%4,%5,%6,%7}, {%8,%9}, {%0,%1,%2,%3};"
                 : "+f"(d0), "+f"(d1), "+f"(d2), "+f"(d3)
                 : "r"(a0), "r"(a1), "r"(a2), "r"(a3), "r"(b0), "r"(b1));
}

// ============ setup: padded tf32 W image + epilogue constants + bnsum zero ===
__global__ void setup_kernel(const float* __restrict__ rW1, const float* __restrict__ rb1,
                             const float* __restrict__ rW2, const float* __restrict__ rb2)
{
    const int tid = threadIdx.x;   // 256
    for (int i = tid; i < 48*128; i += 256) {
        int k = i >> 7, j = i & 127;
        float v = 0.0f;
        if (k < 41 && j < 123) {
            int l = j / 41, jj = j - l*41;
            v = rW1[(l*41 + k)*41 + jj];
        }
        g_Wpad[i] = __uint_as_float(to_tf32(v));
    }
    if (tid < 128) {
        float b1 = 0.0f, w2 = 0.0f;
        if (tid < 123) {
            int l = tid / 41, jj = tid - l*41;
            b1 = rb1[l*41 + jj];
            w2 = rW2[(l*41 + jj)*9] * (Y0C / (float)MNBR);
        }
        g_epib1[tid] = b1;
        g_epiw2[tid] = w2;
    }
    if (tid < 3) g_epir0[tid] = rb2[tid*9] * (Y0C / (float)MNBR);
    for (int i = tid; i < NCONVL*2*FDIM; i += 256) g_bnsum[i] = 0.0f;
}

// ============ edge kernel: mma.sync tf32, 64 edges per CTA ====================
__global__ __launch_bounds__(128, 3) void edge_mma_kernel(const float* __restrict__ nbr_fea)
{
    __shared__ float sA[64*52];
    __shared__ float sRed[4][64*3];
    const int tid  = threadIdx.x;
    const int wid  = tid >> 5, lane = tid & 31;
    const int g    = lane >> 2, q = lane & 3;
    const int base = blockIdx.x * 64;

    const float* src = nbr_fea + (size_t)base * NBRD;
    for (int i = tid; i < 64*NBRD; i += 128) {
        int r = i / NBRD, c = i - r*NBRD;
        sA[r*52 + c] = __uint_as_float(to_tf32(src[i]));
    }
    for (int i = tid; i < 64*7; i += 128) {
        int r = i / 7, c = 41 + (i - r*7);
        sA[r*52 + c] = 0.0f;
    }

    const int wbase = wid * 32;
    uint32_t bf[6][4][2];
    #pragma unroll
    for (int k = 0; k < 6; k++)
        #pragma unroll
        for (int nt = 0; nt < 4; nt++) {
            int col = wbase + nt*8 + g;
            bf[k][nt][0] = __float_as_uint(g_Wpad[(k*8 + q)*128 + col]);
            bf[k][nt][1] = __float_as_uint(g_Wpad[(k*8 + q + 4)*128 + col]);
        }
    float b1a[4], b1b[4], w2a[4], w2b[4];
    int lyA[4], lyB[4];
    #pragma unroll
    for (int nt = 0; nt < 4; nt++) {
        int ja = wbase + nt*8 + q*2, jb = ja + 1;
        b1a[nt] = g_epib1[ja]; b1b[nt] = g_epib1[jb];
        w2a[nt] = g_epiw2[ja]; w2b[nt] = g_epiw2[jb];
        lyA[nt] = (ja < 41) ? 0 : ((ja < 82) ? 1 : 2);
        lyB[nt] = (jb < 41) ? 0 : ((jb < 82) ? 1 : 2);
    }
    __syncthreads();

    #pragma unroll
    for (int m = 0; m < 4; m++) {
        float d[4][4];
        #pragma unroll
        for (int nt = 0; nt < 4; nt++)
            #pragma unroll
            for (int f = 0; f < 4; f++) d[nt][f] = 0.0f;

        const int row0 = m*16 + g, row1 = row0 + 8;
        #pragma unroll
        for (int k = 0; k < 6; k++) {
            uint32_t a0 = __float_as_uint(sA[row0*52 + k*8 + q]);
            uint32_t a1 = __float_as_uint(sA[row1*52 + k*8 + q]);
            uint32_t a2 = __float_as_uint(sA[row0*52 + k*8 + q + 4]);
            uint32_t a3 = __float_as_uint(sA[row1*52 + k*8 + q + 4]);
            #pragma unroll
            for (int nt = 0; nt < 4; nt++)
                mma_tf32(d[nt][0], d[nt][1], d[nt][2], d[nt][3],
                         a0, a1, a2, a3, bf[k][nt][0], bf[k][nt][1]);
        }

        float aA0 = 0.0f, aA1 = 0.0f, aA2 = 0.0f;
        float aB0 = 0.0f, aB1 = 0.0f, aB2 = 0.0f;
        #pragma unroll
        for (int nt = 0; nt < 4; nt++) {
            float v00 = softplus_f(d[nt][0] + b1a[nt]) * w2a[nt];
            float v01 = softplus_f(d[nt][1] + b1b[nt]) * w2b[nt];
            float v10 = softplus_f(d[nt][2] + b1a[nt]) * w2a[nt];
            float v11 = softplus_f(d[nt][3] + b1b[nt]) * w2b[nt];
            if (lyA[nt] == 0) { aA0 += v00; aB0 += v10; }
            else if (lyA[nt] == 1) { aA1 += v00; aB1 += v10; }
            else { aA2 += v00; aB2 += v10; }
            if (lyB[nt] == 0) { aA0 += v01; aB0 += v11; }
            else if (lyB[nt] == 1) { aA1 += v01; aB1 += v11; }
            else { aA2 += v01; aB2 += v11; }
        }
        #pragma unroll
        for (int s = 1; s <= 2; s <<= 1) {
            aA0 += __shfl_xor_sync(0xffffffffu, aA0, s);
            aA1 += __shfl_xor_sync(0xffffffffu, aA1, s);
            aA2 += __shfl_xor_sync(0xffffffffu, aA2, s);
            aB0 += __shfl_xor_sync(0xffffffffu, aB0, s);
            aB1 += __shfl_xor_sync(0xffffffffu, aB1, s);
            aB2 += __shfl_xor_sync(0xffffffffu, aB2, s);
        }
        if (q == 0) {
            sRed[wid][row0*3 + 0] = aA0;
            sRed[wid][row0*3 + 1] = aA1;
            sRed[wid][row0*3 + 2] = aA2;
            sRed[wid][row1*3 + 0] = aB0;
            sRed[wid][row1*3 + 1] = aB1;
            sRed[wid][row1*3 + 2] = aB2;
        }
    }
    __syncthreads();

    for (int i = tid; i < 64*3; i += 128) {
        int row = i / 3, ly = i - row*3;
        float s = sRed[0][i] + sRed[1][i] + sRed[2][i] + sRed[3][i];
        g_w0[ly*NEDGE + base + row] = s + g_epir0[ly];
    }
}

// =============== embedding: x = atom_fea @ emb_W + emb_b (f32x2) =============
__global__ __launch_bounds__(256) void embed_kernel(
    const float* __restrict__ A, const float* __restrict__ W, const float* __restrict__ bias)
{
    __shared__ float sA[64*93];
    __shared__ __align__(16) float sW[92*64];
    __shared__ float sB[64];
    const int tid = threadIdx.x;
    const int row0 = blockIdx.x * 64;
    for (int i = tid; i < 64*92; i += 256) {
        int r = i / 92, k = i % 92;
        int row = row0 + r;
        sA[r*93 + k] = (row < NATOMS) ? A[row*92 + k] : 0.0f;
    }
    for (int i = tid; i < 92*64; i += 256) sW[i] = W[i];
    if (tid < 64) sB[tid] = bias[tid];
    __syncthreads();
    const int tx = tid & 15, ty = tid >> 4;
    unsigned long long acc[4][2];
    #pragma unroll
    for (int i = 0; i < 4; i++) { acc[i][0] = 0ULL; acc[i][1] = 0ULL; }
    #pragma unroll 4
    for (int k = 0; k < 92; k++) {
        ulonglong2 wv = *(const ulonglong2*)(sW + k*64 + (tx << 2));
        #pragma unroll
        for (int i = 0; i < 4; i++) {
            float a = sA[(ty*4 + i)*93 + k];
            unsigned long long a2; SPLAT2(a2, a);
            FFMA2(acc[i][0], wv.x, a2);
            FFMA2(acc[i][1], wv.y, a2);
        }
    }
    #pragma unroll
    for (int i = 0; i < 4; i++) {
        int row = row0 + ty*4 + i;
        if (row < NATOMS) {
            float4 o;
            UNPACK2(o.x, o.y, acc[i][0]);
            UNPACK2(o.z, o.w, acc[i][1]);
            o.x += sB[tx*4+0]; o.y += sB[tx*4+1];
            o.z += sB[tx*4+2]; o.w += sB[tx*4+3];
            *(float4*)(g_x + row*64 + (tx << 2)) = o;
        }
    }
}

// ====== fused layer kernel: gather + conv GEMM + y write + BN stats ==========
// s[r,f] = sum_m w0[l][n,m] * x[nbr[n,m], f];  y = x + s @ (tpW*TPN);
// block accumulates per-column sum/sumsq of y into g_bnsum[l].
__global__ __launch_bounds__(256) void conv_fused_kernel(
    const float* __restrict__ tpW, const int* __restrict__ nbr_idx, int l)
{
    __shared__ float sS[64*65];
    __shared__ __align__(16) float sW[64*64];
    __shared__ float sStat[2*64];
    const int tid = threadIdx.x;
    const int row0 = blockIdx.x * 64;

    for (int i = tid; i < 64*64; i += 256) sW[i] = tpW[l*4096 + i] * TPN;
    if (tid < 128) sStat[tid] = 0.0f;

    // ---- gather phase: 4 row-groups x 64 feats ----
    {
        const int rg = tid >> 6, f = tid & 63;
        const float* w0l = g_w0 + (size_t)l*NEDGE;
        #pragma unroll 4
        for (int r = rg; r < 64; r += 4) {
            const int n = row0 + r;
            float acc = 0.0f;
            if (n < NATOMS) {
                const int*   ip = nbr_idx + n*MNBR;
                const float* wp = w0l + n*MNBR;
                #pragma unroll
                for (int m = 0; m < MNBR; m++)
                    acc = fmaf(wp[m], g_x[ip[m]*64 + f], acc);
            }
            sS[r*65 + f] = acc;
        }
    }
    __syncthreads();

    // ---- GEMM phase ----
    const int tx = tid & 15, ty = tid >> 4;
    unsigned long long acc[4][2];
    #pragma unroll
    for (int i = 0; i < 4; i++) { acc[i][0] = 0ULL; acc[i][1] = 0ULL; }
    #pragma unroll 4
    for (int k = 0; k < 64; k++) {
        ulonglong2 wv = *(const ulonglong2*)(sW + k*64 + (tx << 2));
        #pragma unroll
        for (int i = 0; i < 4; i++) {
            float a = sS[(ty*4 + i)*65 + k];
            unsigned long long a2; SPLAT2(a2, a);
            FFMA2(acc[i][0], wv.x, a2);
            FFMA2(acc[i][1], wv.y, a2);
        }
    }

    // ---- epilogue: residual add, y write, stats ----
    float csum[4] = {0,0,0,0}, csq[4] = {0,0,0,0};
    #pragma unroll
    for (int i = 0; i < 4; i++) {
        int row = row0 + ty*4 + i;
        if (row < NATOMS) {
            float4 xv = *(const float4*)(g_x + row*64 + (tx << 2));
            float4 o;
            UNPACK2(o.x, o.y, acc[i][0]);
            UNPACK2(o.z, o.w, acc[i][1]);
            o.x += xv.x; o.y += xv.y; o.z += xv.z; o.w += xv.w;
            *(float4*)(g_y + row*64 + (tx << 2)) = o;
            csum[0] += o.x; csq[0] = fmaf(o.x, o.x, csq[0]);
            csum[1] += o.y; csq[1] = fmaf(o.y, o.y, csq[1]);
            csum[2] += o.z; csq[2] = fmaf(o.z, o.z, csq[2]);
            csum[3] += o.w; csq[3] = fmaf(o.w, o.w, csq[3]);
        }
    }
    __syncthreads();   // sStat init visible (done before gather, but cheap safety)
    #pragma unroll
    for (int j = 0; j < 4; j++) {
        atomicAdd(&sStat[tx*4 + j], csum[j]);
        atomicAdd(&sStat[64 + tx*4 + j], csq[j]);
    }
    __syncthreads();
    if (tid < 128) atomicAdd(&g_bnsum[l*128 + tid], sStat[tid]);
}

// =============== BN apply + softplus -> new x ================================
__global__ void bn_kernel(const float* __restrict__ gamma, const float* __restrict__ beta, int l)
{
    __shared__ float ssc[64], ssh[64];
    const int tid = threadIdx.x;  // 256
    if (tid < 64) {
        float mu  = g_bnsum[l*128 + tid] * (1.0f/NATOMS);
        float var = g_bnsum[l*128 + 64 + tid] * (1.0f/NATOMS) - mu*mu;
        float sc  = gamma[l*64 + tid] * rsqrtf(var + EPSB);
        ssc[tid] = sc;
        ssh[tid] = beta[l*64 + tid] - mu*sc;
    }
    __syncthreads();
    const int total4 = NATOMS*FDIM/4;
    for (int i = blockIdx.x*256 + tid; i < total4; i += gridDim.x*256) {
        float4 v = ((const float4*)g_y)[i];
        int c = (i & 15) << 2;
        v.x = softplus_f(fmaf(ssc[c+0], v.x, ssh[c+0]));
        v.y = softplus_f(fmaf(ssc[c+1], v.y, ssh[c+1]));
        v.z = softplus_f(fmaf(ssc[c+2], v.z, ssh[c+2]));
        v.w = softplus_f(fmaf(ssc[c+3], v.w, ssh[c+3]));
        ((float4*)g_x)[i] = v;
    }
}

// =============== pooling + MLP head =========================================
__global__ __launch_bounds__(128) void head_kernel(
    const int* __restrict__ cidx, const float* __restrict__ fcW, const float* __restrict__ fcb,
    const float* __restrict__ outW, const float* __restrict__ outb, float* __restrict__ out)
{
    __shared__ float spart[128];
    __shared__ float crys[64];
    __shared__ float hred[128];
    const int b = blockIdx.x, tid = threadIdx.x;
    const int f = tid & 63, half = tid >> 6;
    const int* ci = cidx + b*NPC + half*(NPC/2);
    float a = 0.0f;
    #pragma unroll 4
    for (int i = 0; i < NPC/2; i++) a += g_x[ci[i]*64 + f];
    spart[tid] = a;
    __syncthreads();
    if (tid < 64) crys[tid] = (spart[tid] + spart[tid + 64]) * (1.0f/NPC);
    __syncthreads();
    float acc = fcb[tid];
    #pragma unroll 8
    for (int k = 0; k < 64; k++) acc = fmaf(crys[k], fcW[k*128 + tid], acc);
    float h = softplus_f(acc);
    out[BQ + b*HFD + tid] = h;
    hred[tid] = h * outW[tid];
    __syncthreads();
    for (int sft = 64; sft > 0; sft >>= 1) {
        if (tid < sft) hred[tid] += hred[tid + sft];
        __syncthreads();
    }
    if (tid == 0) out[b] = hred[0] + outb[0];
}

// ============================================================================
extern "C" void kernel_launch(void* const* d_in, const int* in_sizes, int n_in,
                              void* d_out, int out_size)
{
    const float* atom_fea = (const float*)d_in[0];
    const float* nbr_fea  = (const float*)d_in[1];
    /* d_in[2] = pos (unused: only Y_0 path contributes) */
    const float* emb_W    = (const float*)d_in[3];
    const float* emb_b    = (const float*)d_in[4];
    const float* rW1      = (const float*)d_in[5];
    const float* rb1      = (const float*)d_in[6];
    const float* rW2      = (const float*)d_in[7];
    const float* rb2      = (const float*)d_in[8];
    const float* tpW      = (const float*)d_in[9];
    const float* bn_gamma = (const float*)d_in[10];
    const float* bn_beta  = (const float*)d_in[11];
    const float* fc_W     = (const float*)d_in[12];
    const float* fc_b     = (const float*)d_in[13];
    const float* out_W    = (const float*)d_in[14];
    const float* out_b    = (const float*)d_in[15];
    const int*   nbr_idx  = (const int*)d_in[16];
    const int*   cidx     = (const int*)d_in[17];
    float* out = (float*)d_out;

    setup_kernel<<<1, 256>>>(rW1, rb1, rW2, rb2);
    embed_kernel<<<(NATOMS + 63)/64, 256>>>(atom_fea, emb_W, emb_b);
    edge_mma_kernel<<<NEDGE/64, 128>>>(nbr_fea);
    for (int l = 0; l < NCONVL; l++) {
        conv_fused_kernel<<<(NATOMS + 63)/64, 256>>>(tpW, nbr_idx, l);
        bn_kernel<<<592, 256>>>(bn_gamma, bn_beta, l);
    }
    head_kernel<<<BQ, 128>>>(cidx, fc_W, fc_b, out_W, out_b, out);
}

// round 9
// speedup vs baseline: 1.9266x; 1.0922x over previous
#include <cuda_runtime.h>
#include <math.h>
#include <stdint.h>

#define NATOMS 100000
#define MNBR   12
#define NEDGE  (NATOMS*MNBR)
#define ORIG   92
#define NBRD   41
#define FDIM   64
#define HFD    128
#define NCONVL 3
#define BQ     500
#define NPC    200
#define Y0C    0.28209479177387814f
#define TPN    0.125f
#define EPSB   1e-5f

#define NTILES (NEDGE/64)     // 18750
#define NBLK   444            // 148 SMs * 3

// ---------------- scratch (no cudaMalloc allowed) ----------------
__device__ float g_x[NATOMS*FDIM];
__device__ float g_y[NATOMS*FDIM];
__device__ float g_w0[3*NEDGE];
__device__ float g_bnsum[NCONVL*2*FDIM];
__device__ float g_Wpad[48*128];
__device__ float g_epib1[128];
__device__ float g_epiw2[128];
__device__ float g_epir0[3];

__device__ __forceinline__ float softplus_f(float z) {
    float t = fabsf(z);
    float e = __expf(-t);
    return fmaxf(z, 0.0f) + __logf(1.0f + e);
}

#define FFMA2(acc, w, x) asm("fma.rn.f32x2 %0, %1, %2, %3;" : "=l"(acc) : "l"(w), "l"(x), "l"(acc))
#define SPLAT2(d, a)     asm("mov.b64 %0, {%1, %1};" : "=l"(d) : "f"(a))
#define UNPACK2(a, b, d) asm("mov.b64 {%0, %1}, %2;" : "=f"(a), "=f"(b) : "l"(d))

__device__ __forceinline__ uint32_t to_tf32(float v) {
    uint32_t t;
    asm("cvt.rna.tf32.f32 %0, %1;" : "=r"(t) : "f"(v));
    return t;
}

__device__ __forceinline__ void mma_tf32(float& d0, float& d1, float& d2, float& d3,
                                         uint32_t a0, uint32_t a1, uint32_t a2, uint32_t a3,
                                         uint32_t b0, uint32_t b1) {
    asm volatile("mma.sync.aligned.m16n8k8.row.col.f32.tf32.tf32.f32 "
                 "{%0,%1,%2,%3}, {%4,%5,%6,%7}, {%8,%9}, {%0,%1,%2,%3};"
                 : "+f"(d0), "+f"(d1), "+f"(d2), "+f"(d3)
                 : "r"(a0), "r"(a1), "r"(a2), "r"(a3), "r"(b0), "r"(b1));
}

// ============ setup: padded tf32 W image + epilogue constants + bnsum zero ===
__global__ void setup_kernel(const float* __restrict__ rW1, const float* __restrict__ rb1,
                             const float* __restrict__ rW2, const float* __restrict__ rb2)
{
    const int tid = threadIdx.x;   // 256
    for (int i = tid; i < 48*128; i += 256) {
        int k = i >> 7, j = i & 127;
        float v = 0.0f;
        if (k < 41 && j < 123) {
            int l = j / 41, jj = j - l*41;
            v = rW1[(l*41 + k)*41 + jj];
        }
        g_Wpad[i] = __uint_as_float(to_tf32(v));
    }
    if (tid < 128) {
        float b1 = 0.0f, w2 = 0.0f;
        if (tid < 123) {
            int l = tid / 41, jj = tid - l*41;
            b1 = rb1[l*41 + jj];
            w2 = rW2[(l*41 + jj)*9] * (Y0C / (float)MNBR);
        }
        g_epib1[tid] = b1;
        g_epiw2[tid] = w2;
    }
    if (tid < 3) g_epir0[tid] = rb2[tid*9] * (Y0C / (float)MNBR);
    for (int i = tid; i < NCONVL*2*FDIM; i += 256) g_bnsum[i] = 0.0f;
}

// ============ edge kernel: persistent, double-buffered, mma.sync tf32 ========
__global__ __launch_bounds__(128, 3) void edge_mma_kernel(const float* __restrict__ nbr_fea)
{
    __shared__ float sA[2][64*52];
    __shared__ float sRed[4][64*3];
    const int tid  = threadIdx.x;
    const int wid  = tid >> 5, lane = tid & 31;
    const int g    = lane >> 2, q = lane & 3;
    const int bid  = blockIdx.x;

    // ---- one-time: B fragments + epilogue constants ----
    const int wbase = wid * 32;
    uint32_t bf[6][4][2];
    #pragma unroll
    for (int k = 0; k < 6; k++)
        #pragma unroll
        for (int nt = 0; nt < 4; nt++) {
            int col = wbase + nt*8 + g;
            bf[k][nt][0] = __float_as_uint(g_Wpad[(k*8 + q)*128 + col]);
            bf[k][nt][1] = __float_as_uint(g_Wpad[(k*8 + q + 4)*128 + col]);
        }
    float b1a[4], b1b[4], w2a[4], w2b[4];
    int lyA[4], lyB[4];
    #pragma unroll
    for (int nt = 0; nt < 4; nt++) {
        int ja = wbase + nt*8 + q*2, jb = ja + 1;
        b1a[nt] = g_epib1[ja]; b1b[nt] = g_epib1[jb];
        w2a[nt] = g_epiw2[ja]; w2b[nt] = g_epiw2[jb];
        lyA[nt] = (ja < 41) ? 0 : ((ja < 82) ? 1 : 2);
        lyB[nt] = (jb < 41) ? 0 : ((jb < 82) ? 1 : 2);
    }
    const float r0c = g_epir0[0], r1c = g_epir0[1], r2c = g_epir0[2];

    // ---- zero K-pad (cols 41..47) in both buffers; never rewritten ----
    for (int i = tid; i < 64*7; i += 128) {
        int r = i / 7, c = 41 + (i - r*7);
        sA[0][r*52 + c] = 0.0f;
        sA[1][r*52 + c] = 0.0f;
    }
    // ---- prologue: stage first tile into buf 0 ----
    {
        const float* src = nbr_fea + (size_t)bid * 2624;
        for (int i = tid; i < 2624; i += 128) {
            int r = i / 41, c = i - r*41;
            sA[0][r*52 + c] = __uint_as_float(to_tf32(src[i]));
        }
    }

    int cur = 0;
    for (int t = bid; t < NTILES; t += NBLK) {
        const int tn = t + NBLK;
        const bool have_next = (tn < NTILES);
        __syncthreads();                       // buf[cur] staged

        // ---- prefetch next tile's A into registers (latency hidden by MMA) ----
        float pf[21];
        if (have_next) {
            const float* src = nbr_fea + (size_t)tn * 2624;
            #pragma unroll
            for (int j = 0; j < 20; j++) pf[j] = src[tid + j*128];
            if (tid < 64) pf[20] = src[tid + 2560];
        }

        // ---- MMA + epilogue on buf[cur] ----
        const float* A = sA[cur];
        #pragma unroll
        for (int m = 0; m < 4; m++) {
            float d[4][4];
            #pragma unroll
            for (int nt = 0; nt < 4; nt++)
                #pragma unroll
                for (int f = 0; f < 4; f++) d[nt][f] = 0.0f;

            const int row0 = m*16 + g, row1 = row0 + 8;
            #pragma unroll
            for (int k = 0; k < 6; k++) {
                uint32_t a0 = __float_as_uint(A[row0*52 + k*8 + q]);
                uint32_t a1 = __float_as_uint(A[row1*52 + k*8 + q]);
                uint32_t a2 = __float_as_uint(A[row0*52 + k*8 + q + 4]);
                uint32_t a3 = __float_as_uint(A[row1*52 + k*8 + q + 4]);
                #pragma unroll
                for (int nt = 0; nt < 4; nt++)
                    mma_tf32(d[nt][0], d[nt][1], d[nt][2], d[nt][3],
                             a0, a1, a2, a3, bf[k][nt][0], bf[k][nt][1]);
            }

            float aA0 = 0.0f, aA1 = 0.0f, aA2 = 0.0f;
            float aB0 = 0.0f, aB1 = 0.0f, aB2 = 0.0f;
            #pragma unroll
            for (int nt = 0; nt < 4; nt++) {
                float v00 = softplus_f(d[nt][0] + b1a[nt]) * w2a[nt];
                float v01 = softplus_f(d[nt][1] + b1b[nt]) * w2b[nt];
                float v10 = softplus_f(d[nt][2] + b1a[nt]) * w2a[nt];
                float v11 = softplus_f(d[nt][3] + b1b[nt]) * w2b[nt];
                if (lyA[nt] == 0) { aA0 += v00; aB0 += v10; }
                else if (lyA[nt] == 1) { aA1 += v00; aB1 += v10; }
                else { aA2 += v00; aB2 += v10; }
                if (lyB[nt] == 0) { aA0 += v01; aB0 += v11; }
                else if (lyB[nt] == 1) { aA1 += v01; aB1 += v11; }
                else { aA2 += v01; aB2 += v11; }
            }
            #pragma unroll
            for (int s = 1; s <= 2; s <<= 1) {
                aA0 += __shfl_xor_sync(0xffffffffu, aA0, s);
                aA1 += __shfl_xor_sync(0xffffffffu, aA1, s);
                aA2 += __shfl_xor_sync(0xffffffffu, aA2, s);
                aB0 += __shfl_xor_sync(0xffffffffu, aB0, s);
                aB1 += __shfl_xor_sync(0xffffffffu, aB1, s);
                aB2 += __shfl_xor_sync(0xffffffffu, aB2, s);
            }
            if (q == 0) {
                sRed[wid][row0*3 + 0] = aA0;
                sRed[wid][row0*3 + 1] = aA1;
                sRed[wid][row0*3 + 2] = aA2;
                sRed[wid][row1*3 + 0] = aB0;
                sRed[wid][row1*3 + 1] = aB1;
                sRed[wid][row1*3 + 2] = aB2;
            }
        }
        __syncthreads();                       // sRed done; buf[cur] consumed

        // ---- combine + write w0 for tile t ----
        const int base = t*64;
        for (int i = tid; i < 64*3; i += 128) {
            int row = i / 3, ly = i - row*3;
            float s = sRed[0][i] + sRed[1][i] + sRed[2][i] + sRed[3][i];
            float r0 = (ly == 0) ? r0c : ((ly == 1) ? r1c : r2c);
            g_w0[ly*NEDGE + base + row] = s + r0;
        }

        // ---- store prefetched tile into other buffer ----
        if (have_next) {
            float* B = sA[cur ^ 1];
            #pragma unroll
            for (int j = 0; j < 20; j++) {
                int idx = tid + j*128;
                int r = idx / 41, c = idx - r*41;
                B[r*52 + c] = __uint_as_float(to_tf32(pf[j]));
            }
            if (tid < 64) {
                int idx = tid + 2560;
                int r = idx / 41, c = idx - r*41;
                B[r*52 + c] = __uint_as_float(to_tf32(pf[20]));
            }
        }
        cur ^= 1;
    }
}

// =============== embedding: x = atom_fea @ emb_W + emb_b (f32x2) =============
__global__ __launch_bounds__(256) void embed_kernel(
    const float* __restrict__ A, const float* __restrict__ W, const float* __restrict__ bias)
{
    __shared__ float sA[64*93];
    __shared__ __align__(16) float sW[92*64];
    __shared__ float sB[64];
    const int tid = threadIdx.x;
    const int row0 = blockIdx.x * 64;
    for (int i = tid; i < 64*92; i += 256) {
        int r = i / 92, k = i % 92;
        int row = row0 + r;
        sA[r*93 + k] = (row < NATOMS) ? A[row*92 + k] : 0.0f;
    }
    for (int i = tid; i < 92*64; i += 256) sW[i] = W[i];
    if (tid < 64) sB[tid] = bias[tid];
    __syncthreads();
    const int tx = tid & 15, ty = tid >> 4;
    unsigned long long acc[4][2];
    #pragma unroll
    for (int i = 0; i < 4; i++) { acc[i][0] = 0ULL; acc[i][1] = 0ULL; }
    #pragma unroll 4
    for (int k = 0; k < 92; k++) {
        ulonglong2 wv = *(const ulonglong2*)(sW + k*64 + (tx << 2));
        #pragma unroll
        for (int i = 0; i < 4; i++) {
            float a = sA[(ty*4 + i)*93 + k];
            unsigned long long a2; SPLAT2(a2, a);
            FFMA2(acc[i][0], wv.x, a2);
            FFMA2(acc[i][1], wv.y, a2);
        }
    }
    #pragma unroll
    for (int i = 0; i < 4; i++) {
        int row = row0 + ty*4 + i;
        if (row < NATOMS) {
            float4 o;
            UNPACK2(o.x, o.y, acc[i][0]);
            UNPACK2(o.z, o.w, acc[i][1]);
            o.x += sB[tx*4+0]; o.y += sB[tx*4+1];
            o.z += sB[tx*4+2]; o.w += sB[tx*4+3];
            *(float4*)(g_x + row*64 + (tx << 2)) = o;
        }
    }
}

// ====== fused layer kernel: gather + tf32 mma GEMM + y write + BN stats ======
__global__ __launch_bounds__(256) void conv_fused_kernel(
    const float* __restrict__ tpW, const int* __restrict__ nbr_idx, int l)
{
    __shared__ float sS[64*68];     // gathered s, tf32 bits, stride 68 (bank-exact)
    __shared__ float sWc[64*68];    // W col-major tf32: sWc[col*68 + k]
    __shared__ float sStat[128];
    const int tid = threadIdx.x;
    const int row0 = blockIdx.x * 64;

    for (int i = tid; i < 64*64; i += 256) {
        int k = i >> 6, col = i & 63;
        sWc[col*68 + k] = __uint_as_float(to_tf32(tpW[l*4096 + i] * TPN));
    }
    if (tid < 128) sStat[tid] = 0.0f;

    // ---- gather phase ----
    {
        const int rg = tid >> 6, f = tid & 63;
        const float* w0l = g_w0 + (size_t)l*NEDGE;
        #pragma unroll 4
        for (int r = rg; r < 64; r += 4) {
            const int n = row0 + r;
            float acc = 0.0f;
            if (n < NATOMS) {
                const int*   ip = nbr_idx + n*MNBR;
                const float* wp = w0l + n*MNBR;
                #pragma unroll
                for (int m = 0; m < MNBR; m++)
                    acc = fmaf(wp[m], g_x[ip[m]*64 + f], acc);
            }
            sS[r*68 + f] = __uint_as_float(to_tf32(acc));
        }
    }
    __syncthreads();

    // ---- tf32 mma GEMM: warp (mt, nh) computes rows mt*16..+15, cols nh*32..+31
    const int lane = tid & 31, w = tid >> 5;
    const int mt = w & 3, nh = w >> 2;
    const int g = lane >> 2, q = lane & 3;
    const int ra = mt*16 + g, rb = ra + 8;

    float d[4][4];
    #pragma unroll
    for (int nt = 0; nt < 4; nt++)
        #pragma unroll
        for (int f = 0; f < 4; f++) d[nt][f] = 0.0f;

    #pragma unroll
    for (int k = 0; k < 8; k++) {
        uint32_t a0 = __float_as_uint(sS[ra*68 + k*8 + q]);
        uint32_t a1 = __float_as_uint(sS[rb*68 + k*8 + q]);
        uint32_t a2 = __float_as_uint(sS[ra*68 + k*8 + q + 4]);
        uint32_t a3 = __float_as_uint(sS[rb*68 + k*8 + q + 4]);
        #pragma unroll
        for (int nt = 0; nt < 4; nt++) {
            const int col = nh*32 + nt*8 + g;
            uint32_t b0 = __float_as_uint(sWc[col*68 + k*8 + q]);
            uint32_t b1 = __float_as_uint(sWc[col*68 + k*8 + q + 4]);
            mma_tf32(d[nt][0], d[nt][1], d[nt][2], d[nt][3], a0, a1, a2, a3, b0, b1);
        }
    }

    // ---- epilogue: residual + y write + column stats ----
    const int gra = row0 + ra, grb = row0 + rb;
    const bool va = gra < NATOMS, vb = grb < NATOMS;
    float s0[4], s1[4], q0[4], q1[4];
    #pragma unroll
    for (int nt = 0; nt < 4; nt++) {
        const int ja = nh*32 + nt*8 + q*2;
        float o00 = 0.0f, o01 = 0.0f, o10 = 0.0f, o11 = 0.0f;
        if (va) {
            o00 = d[nt][0] + g_x[gra*64 + ja];
            o01 = d[nt][1] + g_x[gra*64 + ja + 1];
            g_y[gra*64 + ja]     = o00;
            g_y[gra*64 + ja + 1] = o01;
        }
        if (vb) {
            o10 = d[nt][2] + g_x[grb*64 + ja];
            o11 = d[nt][3] + g_x[grb*64 + ja + 1];
            g_y[grb*64 + ja]     = o10;
            g_y[grb*64 + ja + 1] = o11;
        }
        s0[nt] = o00 + o10;
        s1[nt] = o01 + o11;
        q0[nt] = o00*o00 + o10*o10;
        q1[nt] = o01*o01 + o11*o11;
    }
    // reduce over g (lane bits 2..4); columns independent of g
    #pragma unroll
    for (int sft = 4; sft <= 16; sft <<= 1) {
        #pragma unroll
        for (int nt = 0; nt < 4; nt++) {
            s0[nt] += __shfl_xor_sync(0xffffffffu, s0[nt], sft);
            s1[nt] += __shfl_xor_sync(0xffffffffu, s1[nt], sft);
            q0[nt] += __shfl_xor_sync(0xffffffffu, q0[nt], sft);
            q1[nt] += __shfl_xor_sync(0xffffffffu, q1[nt], sft);
        }
    }
    if (g == 0) {
        #pragma unroll
        for (int nt = 0; nt < 4; nt++) {
            const int ja = nh*32 + nt*8 + q*2;
            atomicAdd(&sStat[ja],          s0[nt]);
            atomicAdd(&sStat[ja + 1],      s1[nt]);
            atomicAdd(&sStat[64 + ja],     q0[nt]);
            atomicAdd(&sStat[64 + ja + 1], q1[nt]);
        }
    }
    __syncthreads();
    if (tid < 128) atomicAdd(&g_bnsum[l*128 + tid], sStat[tid]);
}

// =============== BN apply + softplus -> new x ================================
__global__ void bn_kernel(const float* __restrict__ gamma, const float* __restrict__ beta, int l)
{
    __shared__ float ssc[64], ssh[64];
    const int tid = threadIdx.x;  // 256
    if (tid < 64) {
        float mu  = g_bnsum[l*128 + tid] * (1.0f/NATOMS);
        float var = g_bnsum[l*128 + 64 + tid] * (1.0f/NATOMS) - mu*mu;
        float sc  = gamma[l*64 + tid] * rsqrtf(var + EPSB);
        ssc[tid] = sc;
        ssh[tid] = beta[l*64 + tid] - mu*sc;
    }
    __syncthreads();
    const int total4 = NATOMS*FDIM/4;
    for (int i = blockIdx.x*256 + tid; i < total4; i += gridDim.x*256) {
        float4 v = ((const float4*)g_y)[i];
        int c = (i & 15) << 2;
        v.x = softplus_f(fmaf(ssc[c+0], v.x, ssh[c+0]));
        v.y = softplus_f(fmaf(ssc[c+1], v.y, ssh[c+1]));
        v.z = softplus_f(fmaf(ssc[c+2], v.z, ssh[c+2]));
        v.w = softplus_f(fmaf(ssc[c+3], v.w, ssh[c+3]));
        ((float4*)g_x)[i] = v;
    }
}

// =============== pooling + MLP head =========================================
__global__ __launch_bounds__(128) void head_kernel(
    const int* __restrict__ cidx, const float* __restrict__ fcW, const float* __restrict__ fcb,
    const float* __restrict__ outW, const float* __restrict__ outb, float* __restrict__ out)
{
    __shared__ float spart[128];
    __shared__ float crys[64];
    __shared__ float hred[128];
    const int b = blockIdx.x, tid = threadIdx.x;
    const int f = tid & 63, half = tid >> 6;
    const int* ci = cidx + b*NPC + half*(NPC/2);
    float a = 0.0f;
    #pragma unroll 4
    for (int i = 0; i < NPC/2; i++) a += g_x[ci[i]*64 + f];
    spart[tid] = a;
    __syncthreads();
    if (tid < 64) crys[tid] = (spart[tid] + spart[tid + 64]) * (1.0f/NPC);
    __syncthreads();
    float acc = fcb[tid];
    #pragma unroll 8
    for (int k = 0; k < 64; k++) acc = fmaf(crys[k], fcW[k*128 + tid], acc);
    float h = softplus_f(acc);
    out[BQ + b*HFD + tid] = h;
    hred[tid] = h * outW[tid];
    __syncthreads();
    for (int sft = 64; sft > 0; sft >>= 1) {
        if (tid < sft) hred[tid] += hred[tid + sft];
        __syncthreads();
    }
    if (tid == 0) out[b] = hred[0] + outb[0];
}

// ============================================================================
extern "C" void kernel_launch(void* const* d_in, const int* in_sizes, int n_in,
                              void* d_out, int out_size)
{
    const float* atom_fea = (const float*)d_in[0];
    const float* nbr_fea  = (const float*)d_in[1];
    /* d_in[2] = pos (unused: only Y_0 path contributes) */
    const float* emb_W    = (const float*)d_in[3];
    const float* emb_b    = (const float*)d_in[4];
    const float* rW1      = (const float*)d_in[5];
    const float* rb1      = (const float*)d_in[6];
    const float* rW2      = (const float*)d_in[7];
    const float* rb2      = (const float*)d_in[8];
    const float* tpW      = (const float*)d_in[9];
    const float* bn_gamma = (const float*)d_in[10];
    const float* bn_beta  = (const float*)d_in[11];
    const float* fc_W     = (const float*)d_in[12];
    const float* fc_b     = (const float*)d_in[13];
    const float* out_W    = (const float*)d_in[14];
    const float* out_b    = (const float*)d_in[15];
    const int*   nbr_idx  = (const int*)d_in[16];
    const int*   cidx     = (const int*)d_in[17];
    float* out = (float*)d_out;

    setup_kernel<<<1, 256>>>(rW1, rb1, rW2, rb2);
    embed_kernel<<<(NATOMS + 63)/64, 256>>>(atom_fea, emb_W, emb_b);
    edge_mma_kernel<<<NBLK, 128>>>(nbr_fea);
    for (int l = 0; l < NCONVL; l++) {
        conv_fused_kernel<<<(NATOMS + 63)/64, 256>>>(tpW, nbr_idx, l);
        bn_kernel<<<592, 256>>>(bn_gamma, bn_beta, l);
    }
    head_kernel<<<BQ, 128>>>(cidx, fc_W, fc_b, out_W, out_b, out);
}

// round 10
// speedup vs baseline: 2.3420x; 1.2156x over previous
#include <cuda_runtime.h>
#include <math.h>
#include <stdint.h>

#define NATOMS 100000
#define MNBR   12
#define NEDGE  (NATOMS*MNBR)
#define ORIG   92
#define NBRD   41
#define FDIM   64
#define HFD    128
#define NCONVL 3
#define BQ     500
#define NPC    200
#define Y0C    0.28209479177387814f
#define TPN    0.125f
#define EPSB   1e-5f

#define NTILES (NEDGE/64)     // 18750
#define NBLK   444            // 148 SMs * 3

// ---------------- scratch (no cudaMalloc allowed) ----------------
__device__ float g_x[NATOMS*FDIM];
__device__ float g_y[NATOMS*FDIM];
__device__ float g_w0[3*NEDGE];
__device__ float g_bnsum[NCONVL*2*FDIM];
__device__ float g_Wpad[48*128];
__device__ float g_Wctf[NCONVL*64*68];   // conv W, tf32, exact smem layout [col*68+k]
__device__ float g_epib1[128];
__device__ float g_epiw2[128];
__device__ float g_epir0[3];

__device__ __forceinline__ float softplus_f(float z) {
    float t = fabsf(z);
    float e = __expf(-t);
    return fmaxf(z, 0.0f) + __logf(1.0f + e);
}

#define FFMA2(acc, w, x) asm("fma.rn.f32x2 %0, %1, %2, %3;" : "=l"(acc) : "l"(w), "l"(x), "l"(acc))
#define SPLAT2(d, a)     asm("mov.b64 %0, {%1, %1};" : "=l"(d) : "f"(a))
#define UNPACK2(a, b, d) asm("mov.b64 {%0, %1}, %2;" : "=f"(a), "=f"(b) : "l"(d))

__device__ __forceinline__ uint32_t to_tf32(float v) {
    uint32_t t;
    asm("cvt.rna.tf32.f32 %0, %1;" : "=r"(t) : "f"(v));
    return t;
}

__device__ __forceinline__ void mma_tf32(float& d0, float& d1, float& d2, float& d3,
                                         uint32_t a0, uint32_t a1, uint32_t a2, uint32_t a3,
                                         uint32_t b0, uint32_t b1) {
    asm volatile("mma.sync.aligned.m16n8k8.row.col.f32.tf32.tf32.f32 "
                 "{%0,%1,%2,%3}, {%4,%5,%6,%7}, {%8,%9}, {%0,%1,%2,%3};"
                 : "+f"(d0), "+f"(d1), "+f"(d2), "+f"(d3)
                 : "r"(a0), "r"(a1), "r"(a2), "r"(a3), "r"(b0), "r"(b1));
}

// ============ setup: edge W image, conv W images, epilogue consts, bnsum zero =
__global__ void setup_kernel(const float* __restrict__ rW1, const float* __restrict__ rb1,
                             const float* __restrict__ rW2, const float* __restrict__ rb2,
                             const float* __restrict__ tpW)
{
    const int tid = threadIdx.x;   // 256
    for (int i = tid; i < 48*128; i += 256) {
        int k = i >> 7, j = i & 127;
        float v = 0.0f;
        if (k < 41 && j < 123) {
            int l = j / 41, jj = j - l*41;
            v = rW1[(l*41 + k)*41 + jj];
        }
        g_Wpad[i] = __uint_as_float(to_tf32(v));
    }
    // conv W: g_Wctf[l][col*68 + k] = tf32(tpW[l][k][col] * TPN), pad k>=64 zero
    for (int i = tid; i < NCONVL*64*68; i += 256) {
        int l = i / (64*68), r = i - l*(64*68);
        int col = r / 68, k = r - col*68;
        float v = (k < 64) ? tpW[l*4096 + k*64 + col] * TPN : 0.0f;
        g_Wctf[i] = __uint_as_float(to_tf32(v));
    }
    if (tid < 128) {
        float b1 = 0.0f, w2 = 0.0f;
        if (tid < 123) {
            int l = tid / 41, jj = tid - l*41;
            b1 = rb1[l*41 + jj];
            w2 = rW2[(l*41 + jj)*9] * (Y0C / (float)MNBR);
        }
        g_epib1[tid] = b1;
        g_epiw2[tid] = w2;
    }
    if (tid < 3) g_epir0[tid] = rb2[tid*9] * (Y0C / (float)MNBR);
    for (int i = tid; i < NCONVL*2*FDIM; i += 256) g_bnsum[i] = 0.0f;
}

// ============ edge kernel: persistent, double-buffered, mma.sync tf32 ========
__global__ __launch_bounds__(128, 3) void edge_mma_kernel(const float* __restrict__ nbr_fea)
{
    __shared__ float sA[2][64*52];
    __shared__ float sRed[4][64*3];
    const int tid  = threadIdx.x;
    const int wid  = tid >> 5, lane = tid & 31;
    const int g    = lane >> 2, q = lane & 3;
    const int bid  = blockIdx.x;

    const int wbase = wid * 32;
    uint32_t bf[6][4][2];
    #pragma unroll
    for (int k = 0; k < 6; k++)
        #pragma unroll
        for (int nt = 0; nt < 4; nt++) {
            int col = wbase + nt*8 + g;
            bf[k][nt][0] = __float_as_uint(g_Wpad[(k*8 + q)*128 + col]);
            bf[k][nt][1] = __float_as_uint(g_Wpad[(k*8 + q + 4)*128 + col]);
        }
    float b1a[4], b1b[4], w2a[4], w2b[4];
    int lyA[4], lyB[4];
    #pragma unroll
    for (int nt = 0; nt < 4; nt++) {
        int ja = wbase + nt*8 + q*2, jb = ja + 1;
        b1a[nt] = g_epib1[ja]; b1b[nt] = g_epib1[jb];
        w2a[nt] = g_epiw2[ja]; w2b[nt] = g_epiw2[jb];
        lyA[nt] = (ja < 41) ? 0 : ((ja < 82) ? 1 : 2);
        lyB[nt] = (jb < 41) ? 0 : ((jb < 82) ? 1 : 2);
    }
    const float r0c = g_epir0[0], r1c = g_epir0[1], r2c = g_epir0[2];

    for (int i = tid; i < 64*7; i += 128) {
        int r = i / 7, c = 41 + (i - r*7);
        sA[0][r*52 + c] = 0.0f;
        sA[1][r*52 + c] = 0.0f;
    }
    {
        const float* src = nbr_fea + (size_t)bid * 2624;
        for (int i = tid; i < 2624; i += 128) {
            int r = i / 41, c = i - r*41;
            sA[0][r*52 + c] = __uint_as_float(to_tf32(src[i]));
        }
    }

    int cur = 0;
    for (int t = bid; t < NTILES; t += NBLK) {
        const int tn = t + NBLK;
        const bool have_next = (tn < NTILES);
        __syncthreads();

        float pf[21];
        if (have_next) {
            const float* src = nbr_fea + (size_t)tn * 2624;
            #pragma unroll
            for (int j = 0; j < 20; j++) pf[j] = src[tid + j*128];
            if (tid < 64) pf[20] = src[tid + 2560];
        }

        const float* A = sA[cur];
        #pragma unroll
        for (int m = 0; m < 4; m++) {
            float d[4][4];
            #pragma unroll
            for (int nt = 0; nt < 4; nt++)
                #pragma unroll
                for (int f = 0; f < 4; f++) d[nt][f] = 0.0f;

            const int row0 = m*16 + g, row1 = row0 + 8;
            #pragma unroll
            for (int k = 0; k < 6; k++) {
                uint32_t a0 = __float_as_uint(A[row0*52 + k*8 + q]);
                uint32_t a1 = __float_as_uint(A[row1*52 + k*8 + q]);
                uint32_t a2 = __float_as_uint(A[row0*52 + k*8 + q + 4]);
                uint32_t a3 = __float_as_uint(A[row1*52 + k*8 + q + 4]);
                #pragma unroll
                for (int nt = 0; nt < 4; nt++)
                    mma_tf32(d[nt][0], d[nt][1], d[nt][2], d[nt][3],
                             a0, a1, a2, a3, bf[k][nt][0], bf[k][nt][1]);
            }

            float aA0 = 0.0f, aA1 = 0.0f, aA2 = 0.0f;
            float aB0 = 0.0f, aB1 = 0.0f, aB2 = 0.0f;
            #pragma unroll
            for (int nt = 0; nt < 4; nt++) {
                float v00 = softplus_f(d[nt][0] + b1a[nt]) * w2a[nt];
                float v01 = softplus_f(d[nt][1] + b1b[nt]) * w2b[nt];
                float v10 = softplus_f(d[nt][2] + b1a[nt]) * w2a[nt];
                float v11 = softplus_f(d[nt][3] + b1b[nt]) * w2b[nt];
                if (lyA[nt] == 0) { aA0 += v00; aB0 += v10; }
                else if (lyA[nt] == 1) { aA1 += v00; aB1 += v10; }
                else { aA2 += v00; aB2 += v10; }
                if (lyB[nt] == 0) { aA0 += v01; aB0 += v11; }
                else if (lyB[nt] == 1) { aA1 += v01; aB1 += v11; }
                else { aA2 += v01; aB2 += v11; }
            }
            #pragma unroll
            for (int s = 1; s <= 2; s <<= 1) {
                aA0 += __shfl_xor_sync(0xffffffffu, aA0, s);
                aA1 += __shfl_xor_sync(0xffffffffu, aA1, s);
                aA2 += __shfl_xor_sync(0xffffffffu, aA2, s);
                aB0 += __shfl_xor_sync(0xffffffffu, aB0, s);
                aB1 += __shfl_xor_sync(0xffffffffu, aB1, s);
                aB2 += __shfl_xor_sync(0xffffffffu, aB2, s);
            }
            if (q == 0) {
                sRed[wid][row0*3 + 0] = aA0;
                sRed[wid][row0*3 + 1] = aA1;
                sRed[wid][row0*3 + 2] = aA2;
                sRed[wid][row1*3 + 0] = aB0;
                sRed[wid][row1*3 + 1] = aB1;
                sRed[wid][row1*3 + 2] = aB2;
            }
        }
        __syncthreads();

        const int base = t*64;
        for (int i = tid; i < 64*3; i += 128) {
            int row = i / 3, ly = i - row*3;
            float s = sRed[0][i] + sRed[1][i] + sRed[2][i] + sRed[3][i];
            float r0 = (ly == 0) ? r0c : ((ly == 1) ? r1c : r2c);
            g_w0[ly*NEDGE + base + row] = s + r0;
        }

        if (have_next) {
            float* B = sA[cur ^ 1];
            #pragma unroll
            for (int j = 0; j < 20; j++) {
                int idx = tid + j*128;
                int r = idx / 41, c = idx - r*41;
                B[r*52 + c] = __uint_as_float(to_tf32(pf[j]));
            }
            if (tid < 64) {
                int idx = tid + 2560;
                int r = idx / 41, c = idx - r*41;
                B[r*52 + c] = __uint_as_float(to_tf32(pf[20]));
            }
        }
        cur ^= 1;
    }
}

// =============== embedding: x = atom_fea @ emb_W + emb_b (f32x2) =============
__global__ __launch_bounds__(256) void embed_kernel(
    const float* __restrict__ A, const float* __restrict__ W, const float* __restrict__ bias)
{
    __shared__ float sA[64*93];
    __shared__ __align__(16) float sW[92*64];
    __shared__ float sB[64];
    const int tid = threadIdx.x;
    const int row0 = blockIdx.x * 64;
    for (int i = tid; i < 64*92; i += 256) {
        int r = i / 92, k = i % 92;
        int row = row0 + r;
        sA[r*93 + k] = (row < NATOMS) ? A[row*92 + k] : 0.0f;
    }
    for (int i = tid; i < 92*64; i += 256) sW[i] = W[i];
    if (tid < 64) sB[tid] = bias[tid];
    __syncthreads();
    const int tx = tid & 15, ty = tid >> 4;
    unsigned long long acc[4][2];
    #pragma unroll
    for (int i = 0; i < 4; i++) { acc[i][0] = 0ULL; acc[i][1] = 0ULL; }
    #pragma unroll 4
    for (int k = 0; k < 92; k++) {
        ulonglong2 wv = *(const ulonglong2*)(sW + k*64 + (tx << 2));
        #pragma unroll
        for (int i = 0; i < 4; i++) {
            float a = sA[(ty*4 + i)*93 + k];
            unsigned long long a2; SPLAT2(a2, a);
            FFMA2(acc[i][0], wv.x, a2);
            FFMA2(acc[i][1], wv.y, a2);
        }
    }
    #pragma unroll
    for (int i = 0; i < 4; i++) {
        int row = row0 + ty*4 + i;
        if (row < NATOMS) {
            float4 o;
            UNPACK2(o.x, o.y, acc[i][0]);
            UNPACK2(o.z, o.w, acc[i][1]);
            o.x += sB[tx*4+0]; o.y += sB[tx*4+1];
            o.z += sB[tx*4+2]; o.w += sB[tx*4+3];
            *(float4*)(g_x + row*64 + (tx << 2)) = o;
        }
    }
}

// ====== fused layer kernel: float4 gather + tf32 mma GEMM + stats ============
__global__ __launch_bounds__(256, 4) void conv_fused_kernel(
    const int* __restrict__ nbr_idx, int l)
{
    __shared__ float sS[64*68];
    __shared__ float sWc[64*68];
    __shared__ int   sIdx[64*12];
    __shared__ float sW0[64*12];
    __shared__ float sStat[128];
    const int tid = threadIdx.x;
    const int row0 = blockIdx.x * 64;

    // ---- stage conv W image (precomputed tf32, exact layout) ----
    {
        const float4* src = (const float4*)(g_Wctf + l*(64*68));
        float4* dst = (float4*)sWc;
        for (int i = tid; i < 64*68/4; i += 256) dst[i] = src[i];
    }
    if (tid < 128) sStat[tid] = 0.0f;

    // ---- stage idx + w0 tiles (coalesced) ----
    {
        const float* w0l = g_w0 + (size_t)l*NEDGE;
        for (int i = tid; i < 64*12; i += 256) {
            int n = row0 + i/12;
            bool v = (n < NATOMS);
            sIdx[i] = v ? nbr_idx[row0*12 + i] : 0;
            sW0[i]  = v ? w0l[row0*12 + i] : 0.0f;
        }
    }
    __syncthreads();

    // ---- gather phase: float4, 16 lanes per row, 8 rows per warp ----
    {
        const int lane = tid & 31, w = tid >> 5;
        const int half = lane >> 4, q4 = lane & 15;
        #pragma unroll
        for (int p = 0; p < 4; p++) {
            const int r = w*8 + p*2 + half;
            float4 acc = make_float4(0.0f, 0.0f, 0.0f, 0.0f);
            #pragma unroll
            for (int m = 0; m < 12; m++) {
                const int nb = sIdx[r*12 + m];
                const float wv = sW0[r*12 + m];
                float4 v = *(const float4*)(g_x + nb*64 + q4*4);
                acc.x = fmaf(wv, v.x, acc.x);
                acc.y = fmaf(wv, v.y, acc.y);
                acc.z = fmaf(wv, v.z, acc.z);
                acc.w = fmaf(wv, v.w, acc.w);
            }
            uint4 t;
            t.x = to_tf32(acc.x); t.y = to_tf32(acc.y);
            t.z = to_tf32(acc.z); t.w = to_tf32(acc.w);
            *(uint4*)(&sS[r*68 + q4*4]) = t;
        }
    }
    __syncthreads();

    // ---- tf32 mma GEMM: warp (mt, nh): rows mt*16..+15, cols nh*32..+31 ----
    const int lane = tid & 31, w = tid >> 5;
    const int mt = w & 3, nh = w >> 2;
    const int g = lane >> 2, q = lane & 3;
    const int ra = mt*16 + g, rb = ra + 8;

    float d[4][4];
    #pragma unroll
    for (int nt = 0; nt < 4; nt++)
        #pragma unroll
        for (int f = 0; f < 4; f++) d[nt][f] = 0.0f;

    #pragma unroll
    for (int k = 0; k < 8; k++) {
        uint32_t a0 = __float_as_uint(sS[ra*68 + k*8 + q]);
        uint32_t a1 = __float_as_uint(sS[rb*68 + k*8 + q]);
        uint32_t a2 = __float_as_uint(sS[ra*68 + k*8 + q + 4]);
        uint32_t a3 = __float_as_uint(sS[rb*68 + k*8 + q + 4]);
        #pragma unroll
        for (int nt = 0; nt < 4; nt++) {
            const int col = nh*32 + nt*8 + g;
            uint32_t b0 = __float_as_uint(sWc[col*68 + k*8 + q]);
            uint32_t b1 = __float_as_uint(sWc[col*68 + k*8 + q + 4]);
            mma_tf32(d[nt][0], d[nt][1], d[nt][2], d[nt][3], a0, a1, a2, a3, b0, b1);
        }
    }

    // ---- epilogue: residual + y write + column stats ----
    const int gra = row0 + ra, grb = row0 + rb;
    const bool va = gra < NATOMS, vb = grb < NATOMS;
    float s0[4], s1[4], q0[4], q1[4];
    #pragma unroll
    for (int nt = 0; nt < 4; nt++) {
        const int ja = nh*32 + nt*8 + q*2;
        float o00 = 0.0f, o01 = 0.0f, o10 = 0.0f, o11 = 0.0f;
        if (va) {
            float2 xv = *(const float2*)(g_x + gra*64 + ja);
            o00 = d[nt][0] + xv.x;
            o01 = d[nt][1] + xv.y;
            *(float2*)(g_y + gra*64 + ja) = make_float2(o00, o01);
        }
        if (vb) {
            float2 xv = *(const float2*)(g_x + grb*64 + ja);
            o10 = d[nt][2] + xv.x;
            o11 = d[nt][3] + xv.y;
            *(float2*)(g_y + grb*64 + ja) = make_float2(o10, o11);
        }
        s0[nt] = o00 + o10;
        s1[nt] = o01 + o11;
        q0[nt] = o00*o00 + o10*o10;
        q1[nt] = o01*o01 + o11*o11;
    }
    #pragma unroll
    for (int sft = 4; sft <= 16; sft <<= 1) {
        #pragma unroll
        for (int nt = 0; nt < 4; nt++) {
            s0[nt] += __shfl_xor_sync(0xffffffffu, s0[nt], sft);
            s1[nt] += __shfl_xor_sync(0xffffffffu, s1[nt], sft);
            q0[nt] += __shfl_xor_sync(0xffffffffu, q0[nt], sft);
            q1[nt] += __shfl_xor_sync(0xffffffffu, q1[nt], sft);
        }
    }
    if (g == 0) {
        #pragma unroll
        for (int nt = 0; nt < 4; nt++) {
            const int ja = nh*32 + nt*8 + q*2;
            atomicAdd(&sStat[ja],          s0[nt]);
            atomicAdd(&sStat[ja + 1],      s1[nt]);
            atomicAdd(&sStat[64 + ja],     q0[nt]);
            atomicAdd(&sStat[64 + ja + 1], q1[nt]);
        }
    }
    __syncthreads();
    if (tid < 128) atomicAdd(&g_bnsum[l*128 + tid], sStat[tid]);
}

// =============== BN apply + softplus -> new x ================================
__global__ void bn_kernel(const float* __restrict__ gamma, const float* __restrict__ beta, int l)
{
    __shared__ float ssc[64], ssh[64];
    const int tid = threadIdx.x;  // 256
    if (tid < 64) {
        float mu  = g_bnsum[l*128 + tid] * (1.0f/NATOMS);
        float var = g_bnsum[l*128 + 64 + tid] * (1.0f/NATOMS) - mu*mu;
        float sc  = gamma[l*64 + tid] * rsqrtf(var + EPSB);
        ssc[tid] = sc;
        ssh[tid] = beta[l*64 + tid] - mu*sc;
    }
    __syncthreads();
    const int total4 = NATOMS*FDIM/4;
    for (int i = blockIdx.x*256 + tid; i < total4; i += gridDim.x*256) {
        float4 v = ((const float4*)g_y)[i];
        int c = (i & 15) << 2;
        v.x = softplus_f(fmaf(ssc[c+0], v.x, ssh[c+0]));
        v.y = softplus_f(fmaf(ssc[c+1], v.y, ssh[c+1]));
        v.z = softplus_f(fmaf(ssc[c+2], v.z, ssh[c+2]));
        v.w = softplus_f(fmaf(ssc[c+3], v.w, ssh[c+3]));
        ((float4*)g_x)[i] = v;
    }
}

// =============== pooling + MLP head =========================================
__global__ __launch_bounds__(128) void head_kernel(
    const int* __restrict__ cidx, const float* __restrict__ fcW, const float* __restrict__ fcb,
    const float* __restrict__ outW, const float* __restrict__ outb, float* __restrict__ out)
{
    __shared__ float spart[128];
    __shared__ float crys[64];
    __shared__ float hred[128];
    const int b = blockIdx.x, tid = threadIdx.x;
    const int f = tid & 63, half = tid >> 6;
    const int* ci = cidx + b*NPC + half*(NPC/2);
    float a = 0.0f;
    #pragma unroll 4
    for (int i = 0; i < NPC/2; i++) a += g_x[ci[i]*64 + f];
    spart[tid] = a;
    __syncthreads();
    if (tid < 64) crys[tid] = (spart[tid] + spart[tid + 64]) * (1.0f/NPC);
    __syncthreads();
    float acc = fcb[tid];
    #pragma unroll 8
    for (int k = 0; k < 64; k++) acc = fmaf(crys[k], fcW[k*128 + tid], acc);
    float h = softplus_f(acc);
    out[BQ + b*HFD + tid] = h;
    hred[tid] = h * outW[tid];
    __syncthreads();
    for (int sft = 64; sft > 0; sft >>= 1) {
        if (tid < sft) hred[tid] += hred[tid + sft];
        __syncthreads();
    }
    if (tid == 0) out[b] = hred[0] + outb[0];
}

// ============================================================================
extern "C" void kernel_launch(void* const* d_in, const int* in_sizes, int n_in,
                              void* d_out, int out_size)
{
    const float* atom_fea = (const float*)d_in[0];
    const float* nbr_fea  = (const float*)d_in[1];
    /* d_in[2] = pos (unused: only Y_0 path contributes) */
    const float* emb_W    = (const float*)d_in[3];
    const float* emb_b    = (const float*)d_in[4];
    const float* rW1      = (const float*)d_in[5];
    const float* rb1      = (const float*)d_in[6];
    const float* rW2      = (const float*)d_in[7];
    const float* rb2      = (const float*)d_in[8];
    const float* tpW      = (const float*)d_in[9];
    const float* bn_gamma = (const float*)d_in[10];
    const float* bn_beta  = (const float*)d_in[11];
    const float* fc_W     = (const float*)d_in[12];
    const float* fc_b     = (const float*)d_in[13];
    const float* out_W    = (const float*)d_in[14];
    const float* out_b    = (const float*)d_in[15];
    const int*   nbr_idx  = (const int*)d_in[16];
    const int*   cidx     = (const int*)d_in[17];
    float* out = (float*)d_out;

    setup_kernel<<<1, 256>>>(rW1, rb1, rW2, rb2, tpW);
    embed_kernel<<<(NATOMS + 63)/64, 256>>>(atom_fea, emb_W, emb_b);
    edge_mma_kernel<<<NBLK, 128>>>(nbr_fea);
    for (int l = 0; l < NCONVL; l++) {
        conv_fused_kernel<<<(NATOMS + 63)/64, 256>>>(nbr_idx, l);
        bn_kernel<<<592, 256>>>(bn_gamma, bn_beta, l);
    }
    head_kernel<<<BQ, 128>>>(cidx, fc_W, fc_b, out_W, out_b, out);
}